// round 12
// baseline (speedup 1.0000x reference)
#include <cuda_runtime.h>
#include <cuda_bf16.h>
#include <math.h>

#define N_NODES  50000
#define N_EDGES  800000
#define HID      128
#define PROJ     512
#define N_CLS    32
#define N_GRAPHS 256
#define T_EMB    768

// ---------------- scratch (static device globals; no runtime alloc) -------
__device__ int   g_cnt[N_NODES];
__device__ float g_dnorm[N_NODES];
__device__ int   g_rowptr[N_NODES + 1];
__device__ int   g_cursor[N_NODES];
__device__ int   g_bsum[256];
__device__ int   g_boff[256];
__device__ int2  g_csre[N_EDGES];   // packed {src_index, float_bits(dnorm[src])}
__device__ float g_xw[N_NODES * HID];
__device__ float g_hbuf[N_NODES * HID];
__device__ float g_stats2[2][2 * HID];   // double-buffered BN raw stats
__device__ float g_gemb[N_GRAPHS * HID];
__device__ float g_p1g[N_GRAPHS * PROJ];
__device__ float g_h2g[N_GRAPHS * PROJ];
__device__ float g_p1t[N_GRAPHS * PROJ];
__device__ float g_h2t[N_GRAPHS * PROJ];

// ---------------- small utility kernels -----------------------------------
__global__ void zero_cnt_k() {
    int i = blockIdx.x * blockDim.x + threadIdx.x;
    if (i < N_NODES) g_cnt[i] = 0;
    if (i < 2 * HID) { g_stats2[0][i] = 0.f; g_stats2[1][i] = 0.f; }
    if (i == 0) g_rowptr[N_NODES] = N_EDGES;
}

__global__ void deg_count_k(const int* __restrict__ dst) {
    int e = blockIdx.x * blockDim.x + threadIdx.x;
    if (e < N_EDGES) atomicAdd(&g_cnt[dst[e]], 1);
}

// block-level exclusive scan pieces (196 blocks x 256 covers 50000)
// also computes dnorm from the counts (fused former dnorm_k).
__global__ void scan_part_k() {
    __shared__ int sh[256];
    int b = blockIdx.x, t = threadIdx.x;
    int idx = b * 256 + t;
    int v = (idx < N_NODES) ? g_cnt[idx] : 0;
    if (idx < N_NODES) g_dnorm[idx] = rsqrtf((float)v + 1.0f);
    sh[t] = v;
    __syncthreads();
    for (int o = 1; o < 256; o <<= 1) {
        int add = (t >= o) ? sh[t - o] : 0;
        __syncthreads();
        sh[t] += add;
        __syncthreads();
    }
    if (idx < N_NODES) g_rowptr[idx] = sh[t] - v;
    if (t == 255) g_bsum[b] = sh[255];
}

__global__ void scan_top_k(int nblocks) {
    __shared__ int sh[256];
    int t = threadIdx.x;
    int v = (t < nblocks) ? g_bsum[t] : 0;
    sh[t] = v;
    __syncthreads();
    for (int o = 1; o < 256; o <<= 1) {
        int add = (t >= o) ? sh[t - o] : 0;
        __syncthreads();
        sh[t] += add;
        __syncthreads();
    }
    g_boff[t] = sh[t] - v;
}

__global__ void scan_add_k() {
    int idx = blockIdx.x * 256 + threadIdx.x;
    if (idx < N_NODES) {
        int rp = g_rowptr[idx] + g_boff[blockIdx.x];
        g_rowptr[idx] = rp;
        g_cursor[idx] = rp;
    }
}

__global__ void scatter_k(const int* __restrict__ src, const int* __restrict__ dst) {
    int e = blockIdx.x * blockDim.x + threadIdx.x;
    if (e < N_EDGES) {
        int s = src[e], d = dst[e];
        int pos = atomicAdd(&g_cursor[d], 1);
        g_csre[pos] = make_int2(s, __float_as_int(g_dnorm[s]));
    }
}

// ---------------- bf16 split helpers ---------------------------------------
// pack two floats into bf16x2: lower half = e0, upper half = e1
__device__ __forceinline__ unsigned pack_bf16x2(float e0, float e1) {
    unsigned r;
    asm("cvt.rn.bf16x2.f32 %0, %1, %2;" : "=r"(r) : "f"(e1), "f"(e0));
    return r;
}
// split a float pair into (hi bf16x2, lo bf16x2); bf16->f32 is an exact shift.
__device__ __forceinline__ void split_pair(float e0, float e1,
                                           unsigned& hi, unsigned& lo) {
    hi = pack_bf16x2(e0, e1);
    float h0 = __uint_as_float(hi << 16);
    float h1 = __uint_as_float(hi & 0xffff0000u);
    lo = pack_bf16x2(e0 - h0, e1 - h1);
}

__device__ __forceinline__ void mma_bf16(float c[4], const unsigned a[4],
                                         unsigned b0, unsigned b1) {
    asm volatile(
        "mma.sync.aligned.m16n8k16.row.col.f32.bf16.bf16.f32 "
        "{%0,%1,%2,%3}, {%4,%5,%6,%7}, {%8,%9}, {%0,%1,%2,%3};"
        : "+f"(c[0]), "+f"(c[1]), "+f"(c[2]), "+f"(c[3])
        : "r"(a[0]), "r"(a[1]), "r"(a[2]), "r"(a[3]), "r"(b0), "r"(b1));
}

// ---------------- node GEMM via 3-term bf16 tensor cores, N-split ----------
// Grid (m_tiles, 2): each CTA computes C[64 x 64] (one n-half), A tile and
// its W half SMEM-resident, k-pair-packed bf16 hi/lo u32 (split once at load;
// mainloop is pure scalar LDS + mma.m16n8k16). smem 70KB -> 3 CTAs/SM.
// Per warp (16 rows x 32 cols): 24 LDS + 12 MMA per k16 step.
// D = Ah*Wh + Ah*Wl + Al*Wh  (error ~2^-17, far under tolerance).
// For layers > 0, applies the previous layer's BN affine (recomputed per
// thread from raw stats) to A at load; resets the other stats buffer.
#define SA_STRIDE 68     // u32 stride, j-dim 64 + pad (mod 32 == 4)
#define SWN 72           // u32 stride, n-dim 64 + pad (mod 32 == 8)
#define A_WORDS (64 * SA_STRIDE)
#define W_WORDS (64 * SWN)
#define GEMM_SMEM ((2 * A_WORDS + 2 * W_WORDS) * 4)

__global__ __launch_bounds__(256) void gemm_node_mma_k(const float* __restrict__ xext,
                                                       int layer0,
                                                       const float* __restrict__ W,
                                                       const float* __restrict__ gamma,
                                                       const float* __restrict__ beta,
                                                       int rb, int zb) {
    extern __shared__ unsigned smem_u[];
    unsigned* sAhi = smem_u;                       // [64 rows][68]  (j = k/2)
    unsigned* sAlo = smem_u + A_WORDS;
    unsigned* sWhi = smem_u + 2 * A_WORDS;         // [64 j][72 n]
    unsigned* sWlo = smem_u + 2 * A_WORDS + W_WORDS;
    const float* A = layer0 ? xext : g_hbuf;
    int bm = blockIdx.x * 64;
    int bn0 = blockIdx.y * 64;                     // n-half base
    int tid = threadIdx.x;

    // per-thread BN coefs for the 4 channels this thread loads
    float scj[4] = {0.f, 0.f, 0.f, 0.f}, shj[4] = {0.f, 0.f, 0.f, 0.f};
    if (!layer0) {
        int c0 = (tid & 31) << 2;
        const float inv = 1.0f / (float)N_NODES;
#pragma unroll
        for (int j = 0; j < 4; j++) {
            float mu = g_stats2[rb][c0 + j] * inv;
            float var = g_stats2[rb][HID + c0 + j] * inv - mu * mu;
            float sc = rsqrtf(var + 1e-5f) * gamma[c0 + j];
            scj[j] = sc;
            shj[j] = beta[c0 + j] - mu * sc;
        }
        // reset the other stats buffer for the upcoming agg (idempotent;
        // both n-half CTAs write the same zeros)
        if (tid < 2 * HID) g_stats2[zb][tid] = 0.f;
    }

    // load A tile (64 rows x 128 k), BN affine fused, split into bf16 hi/lo
#pragma unroll
    for (int i = 0; i < 8; i++) {
        int t = tid + i * 256;           // 2048 float4 slots
        int r = t >> 5, c4 = (t & 31) << 2;   // k start (multiple of 4)
        int row = bm + r;
        float4 v = make_float4(0.f, 0.f, 0.f, 0.f);
        if (row < N_NODES) v = *(const float4*)&A[row * 128 + c4];
        if (!layer0) {
            v.x = fmaf(v.x, scj[0], shj[0]);
            v.y = fmaf(v.y, scj[1], shj[1]);
            v.z = fmaf(v.z, scj[2], shj[2]);
            v.w = fmaf(v.w, scj[3], shj[3]);
        }
        uint2 hi, lo;
        split_pair(v.x, v.y, hi.x, lo.x);
        split_pair(v.z, v.w, hi.y, lo.y);
        int joff = r * SA_STRIDE + (c4 >> 1);
        *(uint2*)&sAhi[joff] = hi;
        *(uint2*)&sAlo[joff] = lo;
    }
    // load W half (128 k x 64 n) as k-pair-packed [j][n], split bf16 hi/lo
#pragma unroll
    for (int i = 0; i < 4; i++) {
        int t = tid + i * 256;           // 1024 (j, n4) slots
        int j = t >> 4, n4 = (t & 15) << 2;
        float4 w0 = *(const float4*)&W[(2 * j) * 128 + bn0 + n4];
        float4 w1 = *(const float4*)&W[(2 * j + 1) * 128 + bn0 + n4];
        uint4 hi, lo;
        split_pair(w0.x, w1.x, hi.x, lo.x);
        split_pair(w0.y, w1.y, hi.y, lo.y);
        split_pair(w0.z, w1.z, hi.z, lo.z);
        split_pair(w0.w, w1.w, hi.w, lo.w);
        int off = j * SWN + n4;
        *(uint4*)&sWhi[off] = hi;
        *(uint4*)&sWlo[off] = lo;
    }
    __syncthreads();

    int w = tid >> 5, lane = tid & 31;
    int g = lane >> 2, tig = lane & 3;
    int r0 = (w & 3) * 16;       // warp row base within tile
    int bn = (w >> 2) * 32;      // warp col base within n-half

    float c[4][4];
#pragma unroll
    for (int t = 0; t < 4; t++)
#pragma unroll
        for (int j = 0; j < 4; j++) c[t][j] = 0.f;

#pragma unroll
    for (int ks = 0; ks < 8; ks++) {       // k16 per step, K=128
        int jb = ks * 8;                   // j = k/2 base
        unsigned ahi[4], alo[4];
        int aoff0 = (r0 + g) * SA_STRIDE + jb + tig;
        int aoff1 = (r0 + g + 8) * SA_STRIDE + jb + tig;
        ahi[0] = sAhi[aoff0];
        ahi[1] = sAhi[aoff1];
        ahi[2] = sAhi[aoff0 + 4];
        ahi[3] = sAhi[aoff1 + 4];
        alo[0] = sAlo[aoff0];
        alo[1] = sAlo[aoff1];
        alo[2] = sAlo[aoff0 + 4];
        alo[3] = sAlo[aoff1 + 4];
#pragma unroll
        for (int t = 0; t < 4; t++) {
            int n = bn + t * 8 + g;
            int woff0 = (jb + tig) * SWN + n;
            int woff1 = (jb + tig + 4) * SWN + n;
            unsigned whi0 = sWhi[woff0];
            unsigned whi1 = sWhi[woff1];
            unsigned wlo0 = sWlo[woff0];
            unsigned wlo1 = sWlo[woff1];
            mma_bf16(c[t], ahi, whi0, whi1);
            mma_bf16(c[t], ahi, wlo0, wlo1);
            mma_bf16(c[t], alo, whi0, whi1);
        }
    }

    // epilogue: c0,c1 -> row g, cols tig*2, tig*2+1 ; c2,c3 -> row g+8
#pragma unroll
    for (int t = 0; t < 4; t++) {
        int n0 = bn0 + bn + t * 8 + tig * 2;
        int row = bm + r0 + g;
        if (row < N_NODES)
            *(float2*)&g_xw[row * 128 + n0] = make_float2(c[t][0], c[t][1]);
        if (row + 8 < N_NODES)
            *(float2*)&g_xw[(row + 8) * 128 + n0] = make_float2(c[t][2], c[t][3]);
    }
}

// ---------------- aggregation + bias + leaky relu + BN stats --------------
// One warp per node, 8 independent row-gathers in flight (L2-latency bound).
__global__ __launch_bounds__(256) void agg_k(const float* __restrict__ bias, int sb) {
    __shared__ float s_sum[HID];
    __shared__ float s_sq[HID];
    int tid = threadIdx.x;
    if (tid < HID) { s_sum[tid] = 0.f; s_sq[tid] = 0.f; }
    __syncthreads();

    int node = blockIdx.x * 8 + (tid >> 5);  // 6250 blocks * 8 warps == 50000
    int lane = tid & 31;
    float dn = g_dnorm[node];
    const float4* base = (const float4*)g_xw;
    float4 self = base[node * 32 + lane];
    float4 a0 = make_float4(0.f, 0.f, 0.f, 0.f);
    float4 a1 = make_float4(0.f, 0.f, 0.f, 0.f);
    float4 a2 = make_float4(0.f, 0.f, 0.f, 0.f);
    float4 a3 = make_float4(0.f, 0.f, 0.f, 0.f);
    int s = g_rowptr[node], e = g_rowptr[node + 1];
    int i = s;
    for (; i + 7 < e; i += 8) {
        int2 c[8];
#pragma unroll
        for (int j = 0; j < 8; j++) c[j] = g_csre[i + j];
        float4 u[8];
#pragma unroll
        for (int j = 0; j < 8; j++) u[j] = base[c[j].x * 32 + lane];
#pragma unroll
        for (int j = 0; j < 8; j++) {
            float w = __int_as_float(c[j].y);
            float4* a = (j & 3) == 0 ? &a0 : (j & 3) == 1 ? &a1 : (j & 3) == 2 ? &a2 : &a3;
            a->x = fmaf(w, u[j].x, a->x);
            a->y = fmaf(w, u[j].y, a->y);
            a->z = fmaf(w, u[j].z, a->z);
            a->w = fmaf(w, u[j].w, a->w);
        }
    }
    for (; i + 3 < e; i += 4) {
        int2 c0 = g_csre[i];
        int2 c1 = g_csre[i + 1];
        int2 c2 = g_csre[i + 2];
        int2 c3 = g_csre[i + 3];
        float4 u0 = base[c0.x * 32 + lane];
        float4 u1 = base[c1.x * 32 + lane];
        float4 u2 = base[c2.x * 32 + lane];
        float4 u3 = base[c3.x * 32 + lane];
        float w0 = __int_as_float(c0.y);
        float w1 = __int_as_float(c1.y);
        float w2 = __int_as_float(c2.y);
        float w3 = __int_as_float(c3.y);
        a0.x = fmaf(w0, u0.x, a0.x); a0.y = fmaf(w0, u0.y, a0.y);
        a0.z = fmaf(w0, u0.z, a0.z); a0.w = fmaf(w0, u0.w, a0.w);
        a1.x = fmaf(w1, u1.x, a1.x); a1.y = fmaf(w1, u1.y, a1.y);
        a1.z = fmaf(w1, u1.z, a1.z); a1.w = fmaf(w1, u1.w, a1.w);
        a2.x = fmaf(w2, u2.x, a2.x); a2.y = fmaf(w2, u2.y, a2.y);
        a2.z = fmaf(w2, u2.z, a2.z); a2.w = fmaf(w2, u2.w, a2.w);
        a3.x = fmaf(w3, u3.x, a3.x); a3.y = fmaf(w3, u3.y, a3.y);
        a3.z = fmaf(w3, u3.z, a3.z); a3.w = fmaf(w3, u3.w, a3.w);
    }
    for (; i < e; i++) {
        int2 cc = g_csre[i];
        float ww = __int_as_float(cc.y);
        float4 u = base[cc.x * 32 + lane];
        a0.x = fmaf(ww, u.x, a0.x); a0.y = fmaf(ww, u.y, a0.y);
        a0.z = fmaf(ww, u.z, a0.z); a0.w = fmaf(ww, u.w, a0.w);
    }
    float4 acc;
    acc.x = (a0.x + a1.x) + (a2.x + a3.x);
    acc.y = (a0.y + a1.y) + (a2.y + a3.y);
    acc.z = (a0.z + a1.z) + (a2.z + a3.z);
    acc.w = (a0.w + a1.w) + (a2.w + a3.w);

    float4 bv = *(const float4*)&bias[lane * 4];
    float dn2 = dn * dn;
    float4 y;
    y.x = dn * acc.x + dn2 * self.x + bv.x;
    y.y = dn * acc.y + dn2 * self.y + bv.y;
    y.z = dn * acc.z + dn2 * self.z + bv.z;
    y.w = dn * acc.w + dn2 * self.w + bv.w;
    // leaky relu 0.01
    y.x = y.x > 0.f ? y.x : 0.01f * y.x;
    y.y = y.y > 0.f ? y.y : 0.01f * y.y;
    y.z = y.z > 0.f ? y.z : 0.01f * y.z;
    y.w = y.w > 0.f ? y.w : 0.01f * y.w;
    *(float4*)&g_hbuf[node * 128 + lane * 4] = y;

    int c = lane * 4;
    atomicAdd(&s_sum[c + 0], y.x);
    atomicAdd(&s_sum[c + 1], y.y);
    atomicAdd(&s_sum[c + 2], y.z);
    atomicAdd(&s_sum[c + 3], y.w);
    atomicAdd(&s_sq[c + 0], y.x * y.x);
    atomicAdd(&s_sq[c + 1], y.y * y.y);
    atomicAdd(&s_sq[c + 2], y.z * y.z);
    atomicAdd(&s_sq[c + 3], y.w * y.w);
    __syncthreads();
    if (tid < HID) {
        atomicAdd(&g_stats2[sb][tid], s_sum[tid]);
        atomicAdd(&g_stats2[sb][HID + tid], s_sq[tid]);
    }
}

// ---------------- mean pool via binary search on sorted batch -------------
// computes the final layer's BN affine per channel and applies it inside
// the pooled sum (linear).
__device__ __forceinline__ int lower_bound_dev(const int* a, int n, int v) {
    int lo = 0, hi = n;
    while (lo < hi) {
        int m = (lo + hi) >> 1;
        if (a[m] < v) lo = m + 1; else hi = m;
    }
    return lo;
}

__global__ void pool_k(const int* __restrict__ batch,
                       const float* __restrict__ gamma,
                       const float* __restrict__ beta, int sb) {
    int g = blockIdx.x;
    __shared__ int se[2];
    if (threadIdx.x == 0) {
        se[0] = lower_bound_dev(batch, N_NODES, g);
        se[1] = lower_bound_dev(batch, N_NODES, g + 1);
    }
    __syncthreads();
    int s = se[0], e = se[1];
    int c = threadIdx.x;  // 128 threads
    const float inv = 1.0f / (float)N_NODES;
    float mu = g_stats2[sb][c] * inv;
    float var = g_stats2[sb][HID + c] * inv - mu * mu;
    float sc = rsqrtf(var + 1e-5f) * gamma[c];
    float sh = beta[c] - mu * sc;
    float acc = 0.f;
    for (int i = s; i < e; i++) acc += g_hbuf[i * 128 + c];
    float n = (float)(e - s);
    float cnt = fmaxf(n, 1.0f);
    g_gemb[g * 128 + c] = (sc * acc + sh * n) / cnt;
}

// ---------------- head GEMM (M=256, N=512, K in {128,512,768}) ------------
__device__ __forceinline__ float gelu_exact(float x) {
    return 0.5f * x * (1.0f + erff(x * 0.70710678118654752f));
}

__global__ __launch_bounds__(256) void gemm_head_k(int which,
                                                   const float* __restrict__ Aext,
                                                   const float* __restrict__ B,
                                                   const float* __restrict__ bias) {
    const float* A;
    float* C;
    const float* res;
    int K;
    bool use_gelu, hasres;
    if (which == 0)      { A = g_gemb; C = g_p1g; res = nullptr; K = 128; use_gelu = false; hasres = false; }
    else if (which == 1) { A = g_p1g;  C = g_h2g; res = g_p1g;   K = 512; use_gelu = true;  hasres = true; }
    else if (which == 2) { A = Aext;   C = g_p1t; res = nullptr; K = 768; use_gelu = false; hasres = false; }
    else                 { A = g_p1t;  C = g_h2t; res = g_p1t;   K = 512; use_gelu = true;  hasres = true; }
    const int N = PROJ;

    __shared__ float As[32][36];
    __shared__ float Bs[32][64];
    int bm = blockIdx.x * 32, bn = blockIdx.y * 64;
    int tid = threadIdx.x;
    int tx = tid & 15;   // cols tx*4
    int ty = tid >> 4;   // rows ty*2
    float acc[2][4];
#pragma unroll
    for (int i = 0; i < 2; i++)
#pragma unroll
        for (int j = 0; j < 4; j++) acc[i][j] = 0.f;

    for (int k0 = 0; k0 < K; k0 += 32) {
        {
            int m = tid >> 3, k4 = (tid & 7) << 2;
            float4 v = *(const float4*)&A[(bm + m) * K + k0 + k4];
            if (use_gelu) {
                v.x = gelu_exact(v.x);
                v.y = gelu_exact(v.y);
                v.z = gelu_exact(v.z);
                v.w = gelu_exact(v.w);
            }
            *(float4*)&As[m][k4] = v;
        }
#pragma unroll
        for (int t = tid; t < 512; t += 256) {
            int k = t >> 4, n4 = (t & 15) << 2;
            *(float4*)&Bs[k][n4] = *(const float4*)&B[(k0 + k) * N + bn + n4];
        }
        __syncthreads();
#pragma unroll
        for (int k = 0; k < 32; k++) {
            float a0 = As[ty * 2 + 0][k];
            float a1 = As[ty * 2 + 1][k];
            float4 b = *(float4*)&Bs[k][tx * 4];
            acc[0][0] = fmaf(a0, b.x, acc[0][0]);
            acc[0][1] = fmaf(a0, b.y, acc[0][1]);
            acc[0][2] = fmaf(a0, b.z, acc[0][2]);
            acc[0][3] = fmaf(a0, b.w, acc[0][3]);
            acc[1][0] = fmaf(a1, b.x, acc[1][0]);
            acc[1][1] = fmaf(a1, b.y, acc[1][1]);
            acc[1][2] = fmaf(a1, b.z, acc[1][2]);
            acc[1][3] = fmaf(a1, b.w, acc[1][3]);
        }
        __syncthreads();
    }
#pragma unroll
    for (int i = 0; i < 2; i++) {
        int row = bm + ty * 2 + i, col = bn + tx * 4;
        float4 bv = *(const float4*)&bias[col];
        float4 o = make_float4(acc[i][0] + bv.x, acc[i][1] + bv.y,
                               acc[i][2] + bv.z, acc[i][3] + bv.w);
        if (hasres) {
            float4 r = *(const float4*)&res[row * N + col];
            o.x += r.x; o.y += r.y; o.z += r.z; o.w += r.w;
        }
        *(float4*)&C[row * N + col] = o;
    }
}

// ---------------- row LayerNorm (512) --------------------------------------
__global__ void layernorm_k(int which, const float* __restrict__ gamma,
                            const float* __restrict__ beta, float* __restrict__ out) {
    const float* X = which ? g_h2t : g_h2g;
    int row = blockIdx.x;
    int tid = threadIdx.x;  // 128 threads, 4 elems each
    float4 v = *(const float4*)&X[row * 512 + tid * 4];
    float s = v.x + v.y + v.z + v.w;
    float q = v.x * v.x + v.y * v.y + v.z * v.z + v.w * v.w;
#pragma unroll
    for (int o = 16; o > 0; o >>= 1) {
        s += __shfl_xor_sync(0xffffffffu, s, o);
        q += __shfl_xor_sync(0xffffffffu, q, o);
    }
    __shared__ float ss[4], qq[4];
    int warp = tid >> 5, lane = tid & 31;
    if (lane == 0) { ss[warp] = s; qq[warp] = q; }
    __syncthreads();
    s = ss[0] + ss[1] + ss[2] + ss[3];
    q = qq[0] + qq[1] + qq[2] + qq[3];
    float mean = s * (1.0f / 512.0f);
    float var = q * (1.0f / 512.0f) - mean * mean;
    float istd = rsqrtf(var + 1e-5f);
    float4 g4 = *(const float4*)&gamma[tid * 4];
    float4 b4 = *(const float4*)&beta[tid * 4];
    float4 o;
    o.x = (v.x - mean) * istd * g4.x + b4.x;
    o.y = (v.y - mean) * istd * g4.y + b4.y;
    o.z = (v.z - mean) * istd * g4.z + b4.z;
    o.w = (v.w - mean) * istd * g4.w + b4.w;
    *(float4*)&out[row * 512 + tid * 4] = o;
}

// ---------------- classifier + log_softmax (warp per row) ------------------
__global__ void cls_k(const float* __restrict__ A, const float* __restrict__ W,
                      const float* __restrict__ b, float* __restrict__ out) {
    int row = blockIdx.x, c = threadIdx.x;  // 32 threads
    float acc = b[c];
    const float* ar = &A[row * 512];
#pragma unroll 8
    for (int k = 0; k < 512; k++) acc = fmaf(ar[k], W[k * 32 + c], acc);
    float mx = acc;
#pragma unroll
    for (int o = 16; o > 0; o >>= 1) mx = fmaxf(mx, __shfl_xor_sync(0xffffffffu, mx, o));
    float l = acc - mx;
    float ex = __expf(l);
    float s = ex;
#pragma unroll
    for (int o = 16; o > 0; o >>= 1) s += __shfl_xor_sync(0xffffffffu, s, o);
    out[row * 32 + c] = l - logf(s);
}

// ---------------- launch ---------------------------------------------------
extern "C" void kernel_launch(void* const* d_in, const int* in_sizes, int n_in,
                              void* d_out, int out_size) {
    const float* x       = (const float*)d_in[0];
    const int*   ei      = (const int*)d_in[1];
    const int*   src     = ei;
    const int*   dst     = ei + N_EDGES;
    const int*   batch   = (const int*)d_in[2];
    const float* text    = (const float*)d_in[3];
    const float* gcn_W   = (const float*)d_in[4];
    const float* gcn_b   = (const float*)d_in[5];
    const float* bn_g    = (const float*)d_in[6];
    const float* bn_b    = (const float*)d_in[7];
    const float* gpj_W1  = (const float*)d_in[8];
    const float* gpj_b1  = (const float*)d_in[9];
    const float* gpj_W2  = (const float*)d_in[10];
    const float* gpj_b2  = (const float*)d_in[11];
    const float* gpj_g   = (const float*)d_in[12];
    const float* gpj_be  = (const float*)d_in[13];
    const float* gcl_W   = (const float*)d_in[14];
    const float* gcl_b   = (const float*)d_in[15];
    const float* tpj_W1  = (const float*)d_in[16];
    const float* tpj_b1  = (const float*)d_in[17];
    const float* tpj_W2  = (const float*)d_in[18];
    const float* tpj_b2  = (const float*)d_in[19];
    const float* tpj_g   = (const float*)d_in[20];
    const float* tpj_be  = (const float*)d_in[21];
    const float* tcl_W   = (const float*)d_in[22];
    const float* tcl_b   = (const float*)d_in[23];
    float* out = (float*)d_out;

    cudaFuncSetAttribute(gemm_node_mma_k,
                         cudaFuncAttributeMaxDynamicSharedMemorySize, GEMM_SMEM);

    dim3 ggrid((N_NODES + 63) / 64, 2);

    // ---- degree + CSR build. gemm L0 is CSR-independent and placed as the
    //      4th launch so ncu's bounded capture profiles the GEMM. ----
    zero_cnt_k<<<196, 256>>>();                                   // #1
    deg_count_k<<<(N_EDGES + 255) / 256, 256>>>(dst);             // #2
    scan_part_k<<<196, 256>>>();                                  // #3 (+dnorm)
    gemm_node_mma_k<<<ggrid, 256, GEMM_SMEM>>>(                   // #4 <- profiled
        x, 1, gcn_W, nullptr, nullptr, 0, 0);
    scan_top_k<<<1, 256>>>(196);                                  // #5
    scan_add_k<<<196, 256>>>();                                   // #6
    scatter_k<<<(N_EDGES + 255) / 256, 256>>>(src, dst);          // #7

    // ---- 4 GCN layers; agg layer l accumulates stats into buf[l&1],
    //      gemm layer l reads buf[(l-1)&1] and zeroes buf[l&1] ----
    agg_k<<<N_NODES / 8, 256>>>(gcn_b, 0);                        // layer 0 agg
    for (int l = 1; l < 4; l++) {
        gemm_node_mma_k<<<ggrid, 256, GEMM_SMEM>>>(
            g_hbuf, 0, gcn_W + l * 128 * 128,
            bn_g + (l - 1) * 128, bn_b + (l - 1) * 128,
            (l - 1) & 1, l & 1);
        agg_k<<<N_NODES / 8, 256>>>(gcn_b + l * 128, l & 1);
    }

    // ---- pool (computes + applies final BN affine, stats buf[1]) ----
    pool_k<<<N_GRAPHS, 128>>>(batch, bn_g + 3 * 128, bn_b + 3 * 128, 1);

    // ---- graph head ----
    dim3 hgrid(N_GRAPHS / 32, PROJ / 64);
    gemm_head_k<<<hgrid, 256>>>(0, nullptr, gpj_W1, gpj_b1);
    gemm_head_k<<<hgrid, 256>>>(1, nullptr, gpj_W2, gpj_b2);
    layernorm_k<<<N_GRAPHS, 128>>>(0, gpj_g, gpj_be, out);                       // graph_proj
    cls_k<<<N_GRAPHS, 32>>>(out, gcl_W, gcl_b, out + 2 * N_GRAPHS * PROJ);       // graph_logp

    // ---- text head ----
    gemm_head_k<<<hgrid, 256>>>(2, text, tpj_W1, tpj_b1);
    gemm_head_k<<<hgrid, 256>>>(3, nullptr, tpj_W2, tpj_b2);
    layernorm_k<<<N_GRAPHS, 128>>>(1, tpj_g, tpj_be, out + N_GRAPHS * PROJ);     // text_proj
    cls_k<<<N_GRAPHS, 32>>>(out + N_GRAPHS * PROJ, tcl_W, tcl_b,
                            out + 2 * N_GRAPHS * PROJ + N_GRAPHS * N_CLS);       // text_logp
}

// round 13
// speedup vs baseline: 1.1514x; 1.1514x over previous
#include <cuda_runtime.h>
#include <cuda_bf16.h>
#include <math.h>

#define N_NODES  50000
#define N_EDGES  800000
#define HID      128
#define PROJ     512
#define N_CLS    32
#define N_GRAPHS 256
#define T_EMB    768

// ---------------- scratch (static device globals; no runtime alloc) -------
__device__ int   g_cnt[N_NODES];
__device__ float g_dnorm[N_NODES];
__device__ int   g_rowptr[N_NODES + 1];
__device__ int   g_cursor[N_NODES];
__device__ int   g_bsum[256];
__device__ int2  g_csre[N_EDGES];   // packed {src_index, float_bits(dnorm[src])}
__device__ float g_xw[N_NODES * HID];
__device__ float g_hbuf[N_NODES * HID];
__device__ float g_stats2[2][2 * HID];   // double-buffered BN raw stats
__device__ float g_gemb[N_GRAPHS * HID];
__device__ float g_p1g[N_GRAPHS * PROJ];
__device__ float g_h2g[N_GRAPHS * PROJ];
__device__ float g_p1t[N_GRAPHS * PROJ];
__device__ float g_h2t[N_GRAPHS * PROJ];

// ---------------- small utility kernels -----------------------------------
__global__ void zero_cnt_k() {
    int i = blockIdx.x * blockDim.x + threadIdx.x;
    if (i < N_NODES) g_cnt[i] = 0;
    if (i < 2 * HID) { g_stats2[0][i] = 0.f; g_stats2[1][i] = 0.f; }
    if (i == 0) g_rowptr[N_NODES] = N_EDGES;
}

__global__ void deg_count_k(const int* __restrict__ dst) {
    int e = blockIdx.x * blockDim.x + threadIdx.x;
    if (e < N_EDGES) atomicAdd(&g_cnt[dst[e]], 1);
}

// block-level exclusive scan (196 blocks x 256 covers 50000); also dnorm.
__global__ void scan_part_k() {
    __shared__ int sh[256];
    int b = blockIdx.x, t = threadIdx.x;
    int idx = b * 256 + t;
    int v = (idx < N_NODES) ? g_cnt[idx] : 0;
    if (idx < N_NODES) g_dnorm[idx] = rsqrtf((float)v + 1.0f);
    sh[t] = v;
    __syncthreads();
    for (int o = 1; o < 256; o <<= 1) {
        int add = (t >= o) ? sh[t - o] : 0;
        __syncthreads();
        sh[t] += add;
        __syncthreads();
    }
    if (idx < N_NODES) g_rowptr[idx] = sh[t] - v;
    if (t == 255) g_bsum[b] = sh[255];
}

// adds the block-prefix of g_bsum (computed in-block) and inits cursors.
// (replaces the separate scan_top kernel)
__global__ void scan_add_k() {
    __shared__ int sh[256];
    int b = blockIdx.x, t = threadIdx.x;
    sh[t] = (t < b) ? g_bsum[t] : 0;
    __syncthreads();
    for (int o = 128; o > 0; o >>= 1) {
        if (t < o) sh[t] += sh[t + o];
        __syncthreads();
    }
    int boff = sh[0];
    int idx = b * 256 + t;
    if (idx < N_NODES) {
        int rp = g_rowptr[idx] + boff;
        g_rowptr[idx] = rp;
        g_cursor[idx] = rp;
    }
}

__global__ void scatter_k(const int* __restrict__ src, const int* __restrict__ dst) {
    int e = blockIdx.x * blockDim.x + threadIdx.x;
    if (e < N_EDGES) {
        int s = src[e], d = dst[e];
        int pos = atomicAdd(&g_cursor[d], 1);
        g_csre[pos] = make_int2(s, __float_as_int(g_dnorm[s]));
    }
}

// ---------------- bf16 split helpers ---------------------------------------
__device__ __forceinline__ unsigned pack_bf16x2(float e0, float e1) {
    unsigned r;
    asm("cvt.rn.bf16x2.f32 %0, %1, %2;" : "=r"(r) : "f"(e1), "f"(e0));
    return r;
}
// split a float pair into (hi bf16x2, lo bf16x2); bf16->f32 is an exact shift.
__device__ __forceinline__ void split_pair(float e0, float e1,
                                           unsigned& hi, unsigned& lo) {
    hi = pack_bf16x2(e0, e1);
    float h0 = __uint_as_float(hi << 16);
    float h1 = __uint_as_float(hi & 0xffff0000u);
    lo = pack_bf16x2(e0 - h0, e1 - h1);
}

__device__ __forceinline__ void mma_bf16(float c[4], const unsigned a[4],
                                         unsigned b0, unsigned b1) {
    asm volatile(
        "mma.sync.aligned.m16n8k16.row.col.f32.bf16.bf16.f32 "
        "{%0,%1,%2,%3}, {%4,%5,%6,%7}, {%8,%9}, {%0,%1,%2,%3};"
        : "+f"(c[0]), "+f"(c[1]), "+f"(c[2]), "+f"(c[3])
        : "r"(a[0]), "r"(a[1]), "r"(a[2]), "r"(a[3]), "r"(b0), "r"(b1));
}

// ---------------- node GEMM via 3-term bf16 tensor cores -------------------
// C[64 x 128] per block (R10 shape, 2 CTAs/SM). hi/lo bf16x2 pairs are
// INTERLEAVED as uint2 in smem so every fragment pair is one LDS.64:
//   sA: uint2 [64 rows][68]   (j = k/2; .x = hi, .y = lo)
//   sW: uint2 [64 j][132 n]
// Mainloop per thread per k16 step: 20 LDS.64 + 24 MMA (was 40 LDS.32).
// D = Ah*Wh + Ah*Wl + Al*Wh  (error ~2^-17, far under tolerance).
// For layers > 0, applies previous layer's BN affine (from raw stats) to A
// at load; resets the other stats buffer for the upcoming agg.
#define SA2 68    // uint2 stride (2*68 mod 32 == 8 -> conflict-free 64b loads)
#define SW2 132   // uint2 stride (2*132 mod 32 == 8)
#define A_U2 (64 * SA2)
#define W_U2 (64 * SW2)
#define GEMM_SMEM ((A_U2 + W_U2) * 8)

__global__ __launch_bounds__(256) void gemm_node_mma_k(const float* __restrict__ xext,
                                                       int layer0,
                                                       const float* __restrict__ W,
                                                       const float* __restrict__ gamma,
                                                       const float* __restrict__ beta,
                                                       int rb, int zb) {
    extern __shared__ uint2 smem_u2[];
    uint2* sA = smem_u2;            // [64][68]
    uint2* sW = smem_u2 + A_U2;     // [64][132]
    const float* A = layer0 ? xext : g_hbuf;
    int bm = blockIdx.x * 64;
    int tid = threadIdx.x;

    // per-thread BN coefs for the 4 channels this thread loads
    float scj[4] = {0.f, 0.f, 0.f, 0.f}, shj[4] = {0.f, 0.f, 0.f, 0.f};
    if (!layer0) {
        int c0 = (tid & 31) << 2;
        const float inv = 1.0f / (float)N_NODES;
#pragma unroll
        for (int j = 0; j < 4; j++) {
            float mu = g_stats2[rb][c0 + j] * inv;
            float var = g_stats2[rb][HID + c0 + j] * inv - mu * mu;
            float sc = rsqrtf(var + 1e-5f) * gamma[c0 + j];
            scj[j] = sc;
            shj[j] = beta[c0 + j] - mu * sc;
        }
        if (tid < 2 * HID) g_stats2[zb][tid] = 0.f;  // idempotent reset
    }

    // load A tile (64 rows x 128 k), BN fused, split+interleave hi/lo
#pragma unroll
    for (int i = 0; i < 8; i++) {
        int t = tid + i * 256;           // 2048 float4 slots
        int r = t >> 5, c4 = (t & 31) << 2;
        int row = bm + r;
        float4 v = make_float4(0.f, 0.f, 0.f, 0.f);
        if (row < N_NODES) v = *(const float4*)&A[row * 128 + c4];
        if (!layer0) {
            v.x = fmaf(v.x, scj[0], shj[0]);
            v.y = fmaf(v.y, scj[1], shj[1]);
            v.z = fmaf(v.z, scj[2], shj[2]);
            v.w = fmaf(v.w, scj[3], shj[3]);
        }
        unsigned h0, l0, h1, l1;
        split_pair(v.x, v.y, h0, l0);
        split_pair(v.z, v.w, h1, l1);
        uint4 pk = make_uint4(h0, l0, h1, l1);   // {hi,lo}(j), {hi,lo}(j+1)
        *(uint4*)&sA[r * SA2 + (c4 >> 1)] = pk;
    }
    // load W (128 k x 128 n) k-pair-packed [j][n], split+interleave hi/lo
#pragma unroll
    for (int i = 0; i < 8; i++) {
        int t = tid + i * 256;           // 2048 (j, n4) slots
        int j = t >> 5, n4 = (t & 31) << 2;
        float4 w0 = *(const float4*)&W[(2 * j) * 128 + n4];
        float4 w1 = *(const float4*)&W[(2 * j + 1) * 128 + n4];
        unsigned hx, lx, hy, ly, hz, lz, hw, lw;
        split_pair(w0.x, w1.x, hx, lx);
        split_pair(w0.y, w1.y, hy, ly);
        split_pair(w0.z, w1.z, hz, lz);
        split_pair(w0.w, w1.w, hw, lw);
        int off = j * SW2 + n4;
        *(uint4*)&sW[off]     = make_uint4(hx, lx, hy, ly);
        *(uint4*)&sW[off + 2] = make_uint4(hz, lz, hw, lw);
    }
    __syncthreads();

    int w = tid >> 5, lane = tid & 31;
    int g = lane >> 2, tig = lane & 3;
    int r0 = (w & 3) * 16;       // warp row base within tile
    int bn = (w >> 2) * 64;      // warp col base

    float c[8][4];
#pragma unroll
    for (int t = 0; t < 8; t++)
#pragma unroll
        for (int j = 0; j < 4; j++) c[t][j] = 0.f;

#pragma unroll
    for (int ks = 0; ks < 8; ks++) {       // k16 per step, K=128
        int jb = ks * 8;                   // j = k/2 base
        uint2 a0 = sA[(r0 + g) * SA2 + jb + tig];
        uint2 a1 = sA[(r0 + g + 8) * SA2 + jb + tig];
        uint2 a2 = sA[(r0 + g) * SA2 + jb + tig + 4];
        uint2 a3 = sA[(r0 + g + 8) * SA2 + jb + tig + 4];
        unsigned ahi[4] = {a0.x, a1.x, a2.x, a3.x};
        unsigned alo[4] = {a0.y, a1.y, a2.y, a3.y};
#pragma unroll
        for (int t = 0; t < 8; t++) {
            int n = bn + t * 8 + g;
            uint2 wv0 = sW[(jb + tig) * SW2 + n];
            uint2 wv1 = sW[(jb + tig + 4) * SW2 + n];
            mma_bf16(c[t], ahi, wv0.x, wv1.x);
            mma_bf16(c[t], ahi, wv0.y, wv1.y);
            mma_bf16(c[t], alo, wv0.x, wv1.x);
        }
    }

    // epilogue: c0,c1 -> row g, cols tig*2, tig*2+1 ; c2,c3 -> row g+8
#pragma unroll
    for (int t = 0; t < 8; t++) {
        int n0 = bn + t * 8 + tig * 2;
        int row = bm + r0 + g;
        if (row < N_NODES)
            *(float2*)&g_xw[row * 128 + n0] = make_float2(c[t][0], c[t][1]);
        if (row + 8 < N_NODES)
            *(float2*)&g_xw[(row + 8) * 128 + n0] = make_float2(c[t][2], c[t][3]);
    }
}

// ---------------- aggregation + bias + leaky relu + BN stats --------------
__global__ __launch_bounds__(256) void agg_k(const float* __restrict__ bias, int sb) {
    __shared__ float s_sum[HID];
    __shared__ float s_sq[HID];
    int tid = threadIdx.x;
    if (tid < HID) { s_sum[tid] = 0.f; s_sq[tid] = 0.f; }
    __syncthreads();

    int node = blockIdx.x * 8 + (tid >> 5);  // 6250 blocks * 8 warps == 50000
    int lane = tid & 31;
    float dn = g_dnorm[node];
    const float4* base = (const float4*)g_xw;
    float4 self = base[node * 32 + lane];
    float4 a0 = make_float4(0.f, 0.f, 0.f, 0.f);
    float4 a1 = make_float4(0.f, 0.f, 0.f, 0.f);
    float4 a2 = make_float4(0.f, 0.f, 0.f, 0.f);
    float4 a3 = make_float4(0.f, 0.f, 0.f, 0.f);
    int s = g_rowptr[node], e = g_rowptr[node + 1];
    int i = s;
    for (; i + 3 < e; i += 4) {
        int2 c0 = g_csre[i];
        int2 c1 = g_csre[i + 1];
        int2 c2 = g_csre[i + 2];
        int2 c3 = g_csre[i + 3];
        float4 u0 = base[c0.x * 32 + lane];
        float4 u1 = base[c1.x * 32 + lane];
        float4 u2 = base[c2.x * 32 + lane];
        float4 u3 = base[c3.x * 32 + lane];
        float w0 = __int_as_float(c0.y);
        float w1 = __int_as_float(c1.y);
        float w2 = __int_as_float(c2.y);
        float w3 = __int_as_float(c3.y);
        a0.x = fmaf(w0, u0.x, a0.x); a0.y = fmaf(w0, u0.y, a0.y);
        a0.z = fmaf(w0, u0.z, a0.z); a0.w = fmaf(w0, u0.w, a0.w);
        a1.x = fmaf(w1, u1.x, a1.x); a1.y = fmaf(w1, u1.y, a1.y);
        a1.z = fmaf(w1, u1.z, a1.z); a1.w = fmaf(w1, u1.w, a1.w);
        a2.x = fmaf(w2, u2.x, a2.x); a2.y = fmaf(w2, u2.y, a2.y);
        a2.z = fmaf(w2, u2.z, a2.z); a2.w = fmaf(w2, u2.w, a2.w);
        a3.x = fmaf(w3, u3.x, a3.x); a3.y = fmaf(w3, u3.y, a3.y);
        a3.z = fmaf(w3, u3.z, a3.z); a3.w = fmaf(w3, u3.w, a3.w);
    }
    for (; i < e; i++) {
        int2 cc = g_csre[i];
        float ww = __int_as_float(cc.y);
        float4 u = base[cc.x * 32 + lane];
        a0.x = fmaf(ww, u.x, a0.x); a0.y = fmaf(ww, u.y, a0.y);
        a0.z = fmaf(ww, u.z, a0.z); a0.w = fmaf(ww, u.w, a0.w);
    }
    float4 acc;
    acc.x = (a0.x + a1.x) + (a2.x + a3.x);
    acc.y = (a0.y + a1.y) + (a2.y + a3.y);
    acc.z = (a0.z + a1.z) + (a2.z + a3.z);
    acc.w = (a0.w + a1.w) + (a2.w + a3.w);

    float4 bv = *(const float4*)&bias[lane * 4];
    float dn2 = dn * dn;
    float4 y;
    y.x = dn * acc.x + dn2 * self.x + bv.x;
    y.y = dn * acc.y + dn2 * self.y + bv.y;
    y.z = dn * acc.z + dn2 * self.z + bv.z;
    y.w = dn * acc.w + dn2 * self.w + bv.w;
    // leaky relu 0.01
    y.x = y.x > 0.f ? y.x : 0.01f * y.x;
    y.y = y.y > 0.f ? y.y : 0.01f * y.y;
    y.z = y.z > 0.f ? y.z : 0.01f * y.z;
    y.w = y.w > 0.f ? y.w : 0.01f * y.w;
    *(float4*)&g_hbuf[node * 128 + lane * 4] = y;

    int c = lane * 4;
    atomicAdd(&s_sum[c + 0], y.x);
    atomicAdd(&s_sum[c + 1], y.y);
    atomicAdd(&s_sum[c + 2], y.z);
    atomicAdd(&s_sum[c + 3], y.w);
    atomicAdd(&s_sq[c + 0], y.x * y.x);
    atomicAdd(&s_sq[c + 1], y.y * y.y);
    atomicAdd(&s_sq[c + 2], y.z * y.z);
    atomicAdd(&s_sq[c + 3], y.w * y.w);
    __syncthreads();
    if (tid < HID) {
        atomicAdd(&g_stats2[sb][tid], s_sum[tid]);
        atomicAdd(&g_stats2[sb][HID + tid], s_sq[tid]);
    }
}

// ---------------- mean pool (binary search on sorted batch) ---------------
__device__ __forceinline__ int lower_bound_dev(const int* a, int n, int v) {
    int lo = 0, hi = n;
    while (lo < hi) {
        int m = (lo + hi) >> 1;
        if (a[m] < v) lo = m + 1; else hi = m;
    }
    return lo;
}

__global__ void pool_k(const int* __restrict__ batch,
                       const float* __restrict__ gamma,
                       const float* __restrict__ beta, int sb) {
    int g = blockIdx.x;
    __shared__ int se[2];
    if (threadIdx.x == 0) {
        se[0] = lower_bound_dev(batch, N_NODES, g);
        se[1] = lower_bound_dev(batch, N_NODES, g + 1);
    }
    __syncthreads();
    int s = se[0], e = se[1];
    int c = threadIdx.x;  // 128 threads
    const float inv = 1.0f / (float)N_NODES;
    float mu = g_stats2[sb][c] * inv;
    float var = g_stats2[sb][HID + c] * inv - mu * mu;
    float sc = rsqrtf(var + 1e-5f) * gamma[c];
    float sh = beta[c] - mu * sc;
    float acc = 0.f;
    for (int i = s; i < e; i++) acc += g_hbuf[i * 128 + c];
    float n = (float)(e - s);
    float cnt = fmaxf(n, 1.0f);
    g_gemb[g * 128 + c] = (sc * acc + sh * n) / cnt;
}

// ---------------- head GEMM (graph/text merged via blockIdx.z) -------------
__device__ __forceinline__ float gelu_exact(float x) {
    return 0.5f * x * (1.0f + erff(x * 0.70710678118654752f));
}

__global__ __launch_bounds__(256) void gemm_head_k(int pair,
                                                   const float* __restrict__ text,
                                                   const float* __restrict__ Bg,
                                                   const float* __restrict__ biasg,
                                                   const float* __restrict__ Bt,
                                                   const float* __restrict__ biast) {
    int which = pair + (blockIdx.z ? 2 : 0);
    const float* B = blockIdx.z ? Bt : Bg;
    const float* bias = blockIdx.z ? biast : biasg;
    const float* A;
    float* C;
    const float* res;
    int K;
    bool use_gelu, hasres;
    if (which == 0)      { A = g_gemb; C = g_p1g; res = nullptr; K = 128; use_gelu = false; hasres = false; }
    else if (which == 1) { A = g_p1g;  C = g_h2g; res = g_p1g;   K = 512; use_gelu = true;  hasres = true; }
    else if (which == 2) { A = text;   C = g_p1t; res = nullptr; K = 768; use_gelu = false; hasres = false; }
    else                 { A = g_p1t;  C = g_h2t; res = g_p1t;   K = 512; use_gelu = true;  hasres = true; }
    const int N = PROJ;

    __shared__ float As[32][36];
    __shared__ float Bs[32][64];
    int bm = blockIdx.x * 32, bn = blockIdx.y * 64;
    int tid = threadIdx.x;
    int tx = tid & 15;   // cols tx*4
    int ty = tid >> 4;   // rows ty*2
    float acc[2][4];
#pragma unroll
    for (int i = 0; i < 2; i++)
#pragma unroll
        for (int j = 0; j < 4; j++) acc[i][j] = 0.f;

    for (int k0 = 0; k0 < K; k0 += 32) {
        {
            int m = tid >> 3, k4 = (tid & 7) << 2;
            float4 v = *(const float4*)&A[(bm + m) * K + k0 + k4];
            if (use_gelu) {
                v.x = gelu_exact(v.x);
                v.y = gelu_exact(v.y);
                v.z = gelu_exact(v.z);
                v.w = gelu_exact(v.w);
            }
            *(float4*)&As[m][k4] = v;
        }
#pragma unroll
        for (int t = tid; t < 512; t += 256) {
            int k = t >> 4, n4 = (t & 15) << 2;
            *(float4*)&Bs[k][n4] = *(const float4*)&B[(k0 + k) * N + bn + n4];
        }
        __syncthreads();
#pragma unroll
        for (int k = 0; k < 32; k++) {
            float a0 = As[ty * 2 + 0][k];
            float a1 = As[ty * 2 + 1][k];
            float4 b = *(float4*)&Bs[k][tx * 4];
            acc[0][0] = fmaf(a0, b.x, acc[0][0]);
            acc[0][1] = fmaf(a0, b.y, acc[0][1]);
            acc[0][2] = fmaf(a0, b.z, acc[0][2]);
            acc[0][3] = fmaf(a0, b.w, acc[0][3]);
            acc[1][0] = fmaf(a1, b.x, acc[1][0]);
            acc[1][1] = fmaf(a1, b.y, acc[1][1]);
            acc[1][2] = fmaf(a1, b.z, acc[1][2]);
            acc[1][3] = fmaf(a1, b.w, acc[1][3]);
        }
        __syncthreads();
    }
#pragma unroll
    for (int i = 0; i < 2; i++) {
        int row = bm + ty * 2 + i, col = bn + tx * 4;
        float4 bv = *(const float4*)&bias[col];
        float4 o = make_float4(acc[i][0] + bv.x, acc[i][1] + bv.y,
                               acc[i][2] + bv.z, acc[i][3] + bv.w);
        if (hasres) {
            float4 r = *(const float4*)&res[row * N + col];
            o.x += r.x; o.y += r.y; o.z += r.z; o.w += r.w;
        }
        *(float4*)&C[row * N + col] = o;
    }
}

// ---------------- fused LayerNorm(512) + classifier + log_softmax ---------
// grid = 512 blocks (256 graph rows then 256 text rows), 128 threads each.
__global__ void ln_cls_k(const float* __restrict__ g_gamma, const float* __restrict__ g_beta,
                         const float* __restrict__ t_gamma, const float* __restrict__ t_beta,
                         const float* __restrict__ g_W, const float* __restrict__ g_b,
                         const float* __restrict__ t_W, const float* __restrict__ t_b,
                         float* __restrict__ out) {
    int rowg = blockIdx.x;
    int which = rowg >> 8;      // 0 = graph, 1 = text
    int row = rowg & 255;
    const float* X = which ? g_h2t : g_h2g;
    const float* gamma = which ? t_gamma : g_gamma;
    const float* beta  = which ? t_beta  : g_beta;
    const float* Wc    = which ? t_W : g_W;
    const float* bc    = which ? t_b : g_b;
    float* proj = out + which * (N_GRAPHS * PROJ) + row * PROJ;
    float* logp = out + 2 * (N_GRAPHS * PROJ) + which * (N_GRAPHS * N_CLS) + row * N_CLS;

    int tid = threadIdx.x;  // 128 threads, 4 elems each
    float4 v = *(const float4*)&X[row * 512 + tid * 4];
    float s = v.x + v.y + v.z + v.w;
    float q = v.x * v.x + v.y * v.y + v.z * v.z + v.w * v.w;
#pragma unroll
    for (int o = 16; o > 0; o >>= 1) {
        s += __shfl_xor_sync(0xffffffffu, s, o);
        q += __shfl_xor_sync(0xffffffffu, q, o);
    }
    __shared__ float ss[4], qq[4];
    __shared__ float srow[512];
    __shared__ float part[4][32];
    int warp = tid >> 5, lane = tid & 31;
    if (lane == 0) { ss[warp] = s; qq[warp] = q; }
    __syncthreads();
    s = ss[0] + ss[1] + ss[2] + ss[3];
    q = qq[0] + qq[1] + qq[2] + qq[3];
    float mean = s * (1.0f / 512.0f);
    float var = q * (1.0f / 512.0f) - mean * mean;
    float istd = rsqrtf(var + 1e-5f);
    float4 g4 = *(const float4*)&gamma[tid * 4];
    float4 b4 = *(const float4*)&beta[tid * 4];
    float4 o;
    o.x = (v.x - mean) * istd * g4.x + b4.x;
    o.y = (v.y - mean) * istd * g4.y + b4.y;
    o.z = (v.z - mean) * istd * g4.z + b4.z;
    o.w = (v.w - mean) * istd * g4.w + b4.w;
    *(float4*)&proj[tid * 4] = o;
    *(float4*)&srow[tid * 4] = o;
    __syncthreads();

    // classifier: quarter q4 = warp, class c = lane
    int c = lane;
    float acc = 0.f;
    const float* wp = Wc + (warp * 128) * 32 + c;
    const float* rp = srow + warp * 128;
#pragma unroll 8
    for (int k = 0; k < 128; k++) acc = fmaf(rp[k], wp[k * 32], acc);
    part[warp][c] = acc;
    __syncthreads();
    if (tid < 32) {
        float l = part[0][tid] + part[1][tid] + part[2][tid] + part[3][tid] + bc[tid];
        float mx = l;
#pragma unroll
        for (int o2 = 16; o2 > 0; o2 >>= 1)
            mx = fmaxf(mx, __shfl_xor_sync(0xffffffffu, mx, o2));
        float lm = l - mx;
        float ex = __expf(lm);
        float sm = ex;
#pragma unroll
        for (int o2 = 16; o2 > 0; o2 >>= 1)
            sm += __shfl_xor_sync(0xffffffffu, sm, o2);
        logp[tid] = lm - logf(sm);
    }
}

// ---------------- launch ---------------------------------------------------
extern "C" void kernel_launch(void* const* d_in, const int* in_sizes, int n_in,
                              void* d_out, int out_size) {
    const float* x       = (const float*)d_in[0];
    const int*   ei      = (const int*)d_in[1];
    const int*   src     = ei;
    const int*   dst     = ei + N_EDGES;
    const int*   batch   = (const int*)d_in[2];
    const float* text    = (const float*)d_in[3];
    const float* gcn_W   = (const float*)d_in[4];
    const float* gcn_b   = (const float*)d_in[5];
    const float* bn_g    = (const float*)d_in[6];
    const float* bn_b    = (const float*)d_in[7];
    const float* gpj_W1  = (const float*)d_in[8];
    const float* gpj_b1  = (const float*)d_in[9];
    const float* gpj_W2  = (const float*)d_in[10];
    const float* gpj_b2  = (const float*)d_in[11];
    const float* gpj_g   = (const float*)d_in[12];
    const float* gpj_be  = (const float*)d_in[13];
    const float* gcl_W   = (const float*)d_in[14];
    const float* gcl_b   = (const float*)d_in[15];
    const float* tpj_W1  = (const float*)d_in[16];
    const float* tpj_b1  = (const float*)d_in[17];
    const float* tpj_W2  = (const float*)d_in[18];
    const float* tpj_b2  = (const float*)d_in[19];
    const float* tpj_g   = (const float*)d_in[20];
    const float* tpj_be  = (const float*)d_in[21];
    const float* tcl_W   = (const float*)d_in[22];
    const float* tcl_b   = (const float*)d_in[23];
    float* out = (float*)d_out;

    cudaFuncSetAttribute(gemm_node_mma_k,
                         cudaFuncAttributeMaxDynamicSharedMemorySize, GEMM_SMEM);

    // ---- degree + CSR build; gemm L0 (CSR-independent) at launch #4 so the
    //      ncu bounded capture profiles the GEMM. ----
    zero_cnt_k<<<196, 256>>>();                                   // #1
    deg_count_k<<<(N_EDGES + 255) / 256, 256>>>(dst);             // #2
    scan_part_k<<<196, 256>>>();                                  // #3 (+dnorm)
    gemm_node_mma_k<<<(N_NODES + 63) / 64, 256, GEMM_SMEM>>>(     // #4 <- profiled
        x, 1, gcn_W, nullptr, nullptr, 0, 0);
    scan_add_k<<<196, 256>>>();                                   // #5 (+scan_top)
    scatter_k<<<(N_EDGES + 255) / 256, 256>>>(src, dst);          // #6

    // ---- 4 GCN layers; agg layer l accumulates stats into buf[l&1],
    //      gemm layer l reads buf[(l-1)&1] and zeroes buf[l&1] ----
    agg_k<<<N_NODES / 8, 256>>>(gcn_b, 0);                        // layer 0 agg
    for (int l = 1; l < 4; l++) {
        gemm_node_mma_k<<<(N_NODES + 63) / 64, 256, GEMM_SMEM>>>(
            g_hbuf, 0, gcn_W + l * 128 * 128,
            bn_g + (l - 1) * 128, bn_b + (l - 1) * 128,
            (l - 1) & 1, l & 1);
        agg_k<<<N_NODES / 8, 256>>>(gcn_b + l * 128, l & 1);
    }

    // ---- pool (computes + applies final BN affine, stats buf[1]) ----
    pool_k<<<N_GRAPHS, 128>>>(batch, bn_g + 3 * 128, bn_b + 3 * 128, 1);

    // ---- heads: graph (z=0) + text (z=1) merged per stage ----
    dim3 hgrid(N_GRAPHS / 32, PROJ / 64, 2);
    gemm_head_k<<<hgrid, 256>>>(0, text, gpj_W1, gpj_b1, tpj_W1, tpj_b1);
    gemm_head_k<<<hgrid, 256>>>(1, text, gpj_W2, gpj_b2, tpj_W2, tpj_b2);
    ln_cls_k<<<2 * N_GRAPHS, 128>>>(gpj_g, gpj_be, tpj_g, tpj_be,
                                    gcl_W, gcl_b, tcl_W, tcl_b, out);
}

// round 14
// speedup vs baseline: 1.2419x; 1.0786x over previous
#include <cuda_runtime.h>
#include <cuda_bf16.h>
#include <math.h>

#define N_NODES  50000
#define N_EDGES  800000
#define HID      128
#define PROJ     512
#define N_CLS    32
#define N_GRAPHS 256
#define T_EMB    768

// ---------------- scratch (static device globals; no runtime alloc) -------
__device__ int   g_cnt[N_NODES];
__device__ float g_dnorm[N_NODES];
__device__ int   g_rowptr[N_NODES + 1];
__device__ int   g_cursor[N_NODES];
__device__ int   g_bsum[256];
__device__ int2  g_csre[N_EDGES];   // packed {src_index, float_bits(dnorm[src])}
__device__ float g_xw[N_NODES * HID];
__device__ float g_hbuf[N_NODES * HID];
__device__ float g_stats2[2][2 * HID];   // double-buffered BN raw stats
__device__ float g_gemb[N_GRAPHS * HID];
__device__ float g_p1g[N_GRAPHS * PROJ];
__device__ float g_h2g[N_GRAPHS * PROJ];
__device__ float g_p1t[N_GRAPHS * PROJ];
__device__ float g_h2t[N_GRAPHS * PROJ];

// ---------------- small utility kernels -----------------------------------
__global__ void zero_cnt_k() {
    int i = blockIdx.x * blockDim.x + threadIdx.x;
    if (i < N_NODES) g_cnt[i] = 0;
    if (i < 2 * HID) { g_stats2[0][i] = 0.f; g_stats2[1][i] = 0.f; }
    if (i == 0) g_rowptr[N_NODES] = N_EDGES;
}

__global__ void deg_count_k(const int* __restrict__ dst) {
    int e = blockIdx.x * blockDim.x + threadIdx.x;
    if (e < N_EDGES) atomicAdd(&g_cnt[dst[e]], 1);
}

// block-level exclusive scan (196 blocks x 256 covers 50000); also dnorm.
__global__ void scan_part_k() {
    __shared__ int sh[256];
    int b = blockIdx.x, t = threadIdx.x;
    int idx = b * 256 + t;
    int v = (idx < N_NODES) ? g_cnt[idx] : 0;
    if (idx < N_NODES) g_dnorm[idx] = rsqrtf((float)v + 1.0f);
    sh[t] = v;
    __syncthreads();
    for (int o = 1; o < 256; o <<= 1) {
        int add = (t >= o) ? sh[t - o] : 0;
        __syncthreads();
        sh[t] += add;
        __syncthreads();
    }
    if (idx < N_NODES) g_rowptr[idx] = sh[t] - v;
    if (t == 255) g_bsum[b] = sh[255];
}

// adds the block-prefix of g_bsum (computed in-block) and inits cursors.
__global__ void scan_add_k() {
    __shared__ int sh[256];
    int b = blockIdx.x, t = threadIdx.x;
    sh[t] = (t < b) ? g_bsum[t] : 0;
    __syncthreads();
    for (int o = 128; o > 0; o >>= 1) {
        if (t < o) sh[t] += sh[t + o];
        __syncthreads();
    }
    int boff = sh[0];
    int idx = b * 256 + t;
    if (idx < N_NODES) {
        int rp = g_rowptr[idx] + boff;
        g_rowptr[idx] = rp;
        g_cursor[idx] = rp;
    }
}

__global__ void scatter_k(const int* __restrict__ src, const int* __restrict__ dst) {
    int e = blockIdx.x * blockDim.x + threadIdx.x;
    if (e < N_EDGES) {
        int s = src[e], d = dst[e];
        int pos = atomicAdd(&g_cursor[d], 1);
        g_csre[pos] = make_int2(s, __float_as_int(g_dnorm[s]));
    }
}

// ---------------- bf16 split helpers ---------------------------------------
__device__ __forceinline__ unsigned pack_bf16x2(float e0, float e1) {
    unsigned r;
    asm("cvt.rn.bf16x2.f32 %0, %1, %2;" : "=r"(r) : "f"(e1), "f"(e0));
    return r;
}
// split a float pair into (hi bf16x2, lo bf16x2); bf16->f32 is an exact shift.
__device__ __forceinline__ void split_pair(float e0, float e1,
                                           unsigned& hi, unsigned& lo) {
    hi = pack_bf16x2(e0, e1);
    float h0 = __uint_as_float(hi << 16);
    float h1 = __uint_as_float(hi & 0xffff0000u);
    lo = pack_bf16x2(e0 - h0, e1 - h1);
}

__device__ __forceinline__ void mma_bf16(float c[4], const unsigned a[4],
                                         unsigned b0, unsigned b1) {
    asm volatile(
        "mma.sync.aligned.m16n8k16.row.col.f32.bf16.bf16.f32 "
        "{%0,%1,%2,%3}, {%4,%5,%6,%7}, {%8,%9}, {%0,%1,%2,%3};"
        : "+f"(c[0]), "+f"(c[1]), "+f"(c[2]), "+f"(c[3])
        : "r"(a[0]), "r"(a[1]), "r"(a[2]), "r"(a[3]), "r"(b0), "r"(b1));
}

// ---------------- node GEMM via 3-term bf16 tensor cores (R10 body) --------
// C[64 x 128] per block; A tile and full W (K=128) split at smem-load time
// into bf16 hi/lo k-pair-packed u32 (separate arrays, scalar LDS mainloop;
// measured-best config). D = Ah*Wh + Ah*Wl + Al*Wh  (error ~2^-17).
// For layers > 0, applies previous layer's BN affine (from raw stats) to A
// at load; resets the other stats buffer for the upcoming agg.
#define SA_STRIDE 68     // u32 stride, j-dim 64 + pad (mod 32 == 4)
#define SW_STRIDE 136    // u32 stride, n-dim 128 + pad (mod 32 == 8)
#define A_WORDS (64 * SA_STRIDE)
#define W_WORDS (64 * SW_STRIDE)
#define GEMM_SMEM ((2 * A_WORDS + 2 * W_WORDS) * 4)

__global__ __launch_bounds__(256) void gemm_node_mma_k(const float* __restrict__ xext,
                                                       int layer0,
                                                       const float* __restrict__ W,
                                                       const float* __restrict__ gamma,
                                                       const float* __restrict__ beta,
                                                       int rb, int zb) {
    extern __shared__ unsigned smem_u[];
    unsigned* sAhi = smem_u;                       // [64 rows][68]  (j = k/2)
    unsigned* sAlo = smem_u + A_WORDS;
    unsigned* sWhi = smem_u + 2 * A_WORDS;         // [64 j][136 n]
    unsigned* sWlo = smem_u + 2 * A_WORDS + W_WORDS;
    const float* A = layer0 ? xext : g_hbuf;
    int bm = blockIdx.x * 64;
    int tid = threadIdx.x;

    // per-thread BN coefs for the 4 channels this thread loads
    float scj[4] = {0.f, 0.f, 0.f, 0.f}, shj[4] = {0.f, 0.f, 0.f, 0.f};
    if (!layer0) {
        int c0 = (tid & 31) << 2;
        const float inv = 1.0f / (float)N_NODES;
#pragma unroll
        for (int j = 0; j < 4; j++) {
            float mu = g_stats2[rb][c0 + j] * inv;
            float var = g_stats2[rb][HID + c0 + j] * inv - mu * mu;
            float sc = rsqrtf(var + 1e-5f) * gamma[c0 + j];
            scj[j] = sc;
            shj[j] = beta[c0 + j] - mu * sc;
        }
        if (tid < 2 * HID) g_stats2[zb][tid] = 0.f;  // idempotent reset
    }

    // load A tile (64 rows x 128 k), BN affine fused, split into bf16 hi/lo
#pragma unroll
    for (int i = 0; i < 8; i++) {
        int t = tid + i * 256;           // 2048 float4 slots
        int r = t >> 5, c4 = (t & 31) << 2;   // k start (multiple of 4)
        int row = bm + r;
        float4 v = make_float4(0.f, 0.f, 0.f, 0.f);
        if (row < N_NODES) v = *(const float4*)&A[row * 128 + c4];
        if (!layer0) {
            v.x = fmaf(v.x, scj[0], shj[0]);
            v.y = fmaf(v.y, scj[1], shj[1]);
            v.z = fmaf(v.z, scj[2], shj[2]);
            v.w = fmaf(v.w, scj[3], shj[3]);
        }
        uint2 hi, lo;
        split_pair(v.x, v.y, hi.x, lo.x);
        split_pair(v.z, v.w, hi.y, lo.y);
        int joff = r * SA_STRIDE + (c4 >> 1);
        *(uint2*)&sAhi[joff] = hi;
        *(uint2*)&sAlo[joff] = lo;
    }
    // load W (128 k x 128 n) as k-pair-packed [j][n], split bf16 hi/lo
#pragma unroll
    for (int i = 0; i < 8; i++) {
        int t = tid + i * 256;           // 2048 (j, n4) slots
        int j = t >> 5, n4 = (t & 31) << 2;
        float4 w0 = *(const float4*)&W[(2 * j) * 128 + n4];
        float4 w1 = *(const float4*)&W[(2 * j + 1) * 128 + n4];
        uint4 hi, lo;
        split_pair(w0.x, w1.x, hi.x, lo.x);
        split_pair(w0.y, w1.y, hi.y, lo.y);
        split_pair(w0.z, w1.z, hi.z, lo.z);
        split_pair(w0.w, w1.w, hi.w, lo.w);
        int off = j * SW_STRIDE + n4;
        *(uint4*)&sWhi[off] = hi;
        *(uint4*)&sWlo[off] = lo;
    }
    __syncthreads();

    int w = tid >> 5, lane = tid & 31;
    int g = lane >> 2, tig = lane & 3;
    int r0 = (w & 3) * 16;       // warp row base within tile
    int bn = (w >> 2) * 64;      // warp col base

    float c[8][4];
#pragma unroll
    for (int t = 0; t < 8; t++)
#pragma unroll
        for (int j = 0; j < 4; j++) c[t][j] = 0.f;

#pragma unroll
    for (int ks = 0; ks < 8; ks++) {       // k16 per step, K=128
        int jb = ks * 8;                   // j = k/2 base
        unsigned ahi[4], alo[4];
        int aoff0 = (r0 + g) * SA_STRIDE + jb + tig;
        int aoff1 = (r0 + g + 8) * SA_STRIDE + jb + tig;
        ahi[0] = sAhi[aoff0];
        ahi[1] = sAhi[aoff1];
        ahi[2] = sAhi[aoff0 + 4];
        ahi[3] = sAhi[aoff1 + 4];
        alo[0] = sAlo[aoff0];
        alo[1] = sAlo[aoff1];
        alo[2] = sAlo[aoff0 + 4];
        alo[3] = sAlo[aoff1 + 4];
#pragma unroll
        for (int t = 0; t < 8; t++) {
            int n = bn + t * 8 + g;
            int woff0 = (jb + tig) * SW_STRIDE + n;
            int woff1 = (jb + tig + 4) * SW_STRIDE + n;
            unsigned whi0 = sWhi[woff0];
            unsigned whi1 = sWhi[woff1];
            unsigned wlo0 = sWlo[woff0];
            unsigned wlo1 = sWlo[woff1];
            mma_bf16(c[t], ahi, whi0, whi1);
            mma_bf16(c[t], ahi, wlo0, wlo1);
            mma_bf16(c[t], alo, whi0, whi1);
        }
    }

    // epilogue: c0,c1 -> row g, cols tig*2, tig*2+1 ; c2,c3 -> row g+8
#pragma unroll
    for (int t = 0; t < 8; t++) {
        int n0 = bn + t * 8 + tig * 2;
        int row = bm + r0 + g;
        if (row < N_NODES)
            *(float2*)&g_xw[row * 128 + n0] = make_float2(c[t][0], c[t][1]);
        if (row + 8 < N_NODES)
            *(float2*)&g_xw[(row + 8) * 128 + n0] = make_float2(c[t][2], c[t][3]);
    }
}

// ---------------- aggregation + bias + leaky relu + BN stats --------------
__global__ __launch_bounds__(256) void agg_k(const float* __restrict__ bias, int sb) {
    __shared__ float s_sum[HID];
    __shared__ float s_sq[HID];
    int tid = threadIdx.x;
    if (tid < HID) { s_sum[tid] = 0.f; s_sq[tid] = 0.f; }
    __syncthreads();

    int node = blockIdx.x * 8 + (tid >> 5);  // 6250 blocks * 8 warps == 50000
    int lane = tid & 31;
    float dn = g_dnorm[node];
    const float4* base = (const float4*)g_xw;
    float4 self = base[node * 32 + lane];
    float4 a0 = make_float4(0.f, 0.f, 0.f, 0.f);
    float4 a1 = make_float4(0.f, 0.f, 0.f, 0.f);
    float4 a2 = make_float4(0.f, 0.f, 0.f, 0.f);
    float4 a3 = make_float4(0.f, 0.f, 0.f, 0.f);
    int s = g_rowptr[node], e = g_rowptr[node + 1];
    int i = s;
    for (; i + 3 < e; i += 4) {
        int2 c0 = g_csre[i];
        int2 c1 = g_csre[i + 1];
        int2 c2 = g_csre[i + 2];
        int2 c3 = g_csre[i + 3];
        float4 u0 = base[c0.x * 32 + lane];
        float4 u1 = base[c1.x * 32 + lane];
        float4 u2 = base[c2.x * 32 + lane];
        float4 u3 = base[c3.x * 32 + lane];
        float w0 = __int_as_float(c0.y);
        float w1 = __int_as_float(c1.y);
        float w2 = __int_as_float(c2.y);
        float w3 = __int_as_float(c3.y);
        a0.x = fmaf(w0, u0.x, a0.x); a0.y = fmaf(w0, u0.y, a0.y);
        a0.z = fmaf(w0, u0.z, a0.z); a0.w = fmaf(w0, u0.w, a0.w);
        a1.x = fmaf(w1, u1.x, a1.x); a1.y = fmaf(w1, u1.y, a1.y);
        a1.z = fmaf(w1, u1.z, a1.z); a1.w = fmaf(w1, u1.w, a1.w);
        a2.x = fmaf(w2, u2.x, a2.x); a2.y = fmaf(w2, u2.y, a2.y);
        a2.z = fmaf(w2, u2.z, a2.z); a2.w = fmaf(w2, u2.w, a2.w);
        a3.x = fmaf(w3, u3.x, a3.x); a3.y = fmaf(w3, u3.y, a3.y);
        a3.z = fmaf(w3, u3.z, a3.z); a3.w = fmaf(w3, u3.w, a3.w);
    }
    for (; i < e; i++) {
        int2 cc = g_csre[i];
        float ww = __int_as_float(cc.y);
        float4 u = base[cc.x * 32 + lane];
        a0.x = fmaf(ww, u.x, a0.x); a0.y = fmaf(ww, u.y, a0.y);
        a0.z = fmaf(ww, u.z, a0.z); a0.w = fmaf(ww, u.w, a0.w);
    }
    float4 acc;
    acc.x = (a0.x + a1.x) + (a2.x + a3.x);
    acc.y = (a0.y + a1.y) + (a2.y + a3.y);
    acc.z = (a0.z + a1.z) + (a2.z + a3.z);
    acc.w = (a0.w + a1.w) + (a2.w + a3.w);

    float4 bv = *(const float4*)&bias[lane * 4];
    float dn2 = dn * dn;
    float4 y;
    y.x = dn * acc.x + dn2 * self.x + bv.x;
    y.y = dn * acc.y + dn2 * self.y + bv.y;
    y.z = dn * acc.z + dn2 * self.z + bv.z;
    y.w = dn * acc.w + dn2 * self.w + bv.w;
    // leaky relu 0.01
    y.x = y.x > 0.f ? y.x : 0.01f * y.x;
    y.y = y.y > 0.f ? y.y : 0.01f * y.y;
    y.z = y.z > 0.f ? y.z : 0.01f * y.z;
    y.w = y.w > 0.f ? y.w : 0.01f * y.w;
    *(float4*)&g_hbuf[node * 128 + lane * 4] = y;

    int c = lane * 4;
    atomicAdd(&s_sum[c + 0], y.x);
    atomicAdd(&s_sum[c + 1], y.y);
    atomicAdd(&s_sum[c + 2], y.z);
    atomicAdd(&s_sum[c + 3], y.w);
    atomicAdd(&s_sq[c + 0], y.x * y.x);
    atomicAdd(&s_sq[c + 1], y.y * y.y);
    atomicAdd(&s_sq[c + 2], y.z * y.z);
    atomicAdd(&s_sq[c + 3], y.w * y.w);
    __syncthreads();
    if (tid < HID) {
        atomicAdd(&g_stats2[sb][tid], s_sum[tid]);
        atomicAdd(&g_stats2[sb][HID + tid], s_sq[tid]);
    }
}

// ---------------- mean pool (binary search on sorted batch) ---------------
__device__ __forceinline__ int lower_bound_dev(const int* a, int n, int v) {
    int lo = 0, hi = n;
    while (lo < hi) {
        int m = (lo + hi) >> 1;
        if (a[m] < v) lo = m + 1; else hi = m;
    }
    return lo;
}

__global__ void pool_k(const int* __restrict__ batch,
                       const float* __restrict__ gamma,
                       const float* __restrict__ beta, int sb) {
    int g = blockIdx.x;
    __shared__ int se[2];
    if (threadIdx.x == 0) {
        se[0] = lower_bound_dev(batch, N_NODES, g);
        se[1] = lower_bound_dev(batch, N_NODES, g + 1);
    }
    __syncthreads();
    int s = se[0], e = se[1];
    int c = threadIdx.x;  // 128 threads
    const float inv = 1.0f / (float)N_NODES;
    float mu = g_stats2[sb][c] * inv;
    float var = g_stats2[sb][HID + c] * inv - mu * mu;
    float sc = rsqrtf(var + 1e-5f) * gamma[c];
    float sh = beta[c] - mu * sc;
    float acc = 0.f;
    for (int i = s; i < e; i++) acc += g_hbuf[i * 128 + c];
    float n = (float)(e - s);
    float cnt = fmaxf(n, 1.0f);
    g_gemb[g * 128 + c] = (sc * acc + sh * n) / cnt;
}

// ---------------- head GEMM (M=256, N=512, K in {128,512,768}) ------------
__device__ __forceinline__ float gelu_exact(float x) {
    return 0.5f * x * (1.0f + erff(x * 0.70710678118654752f));
}

__global__ __launch_bounds__(256) void gemm_head_k(int which,
                                                   const float* __restrict__ Aext,
                                                   const float* __restrict__ B,
                                                   const float* __restrict__ bias) {
    const float* A;
    float* C;
    const float* res;
    int K;
    bool use_gelu, hasres;
    if (which == 0)      { A = g_gemb; C = g_p1g; res = nullptr; K = 128; use_gelu = false; hasres = false; }
    else if (which == 1) { A = g_p1g;  C = g_h2g; res = g_p1g;   K = 512; use_gelu = true;  hasres = true; }
    else if (which == 2) { A = Aext;   C = g_p1t; res = nullptr; K = 768; use_gelu = false; hasres = false; }
    else                 { A = g_p1t;  C = g_h2t; res = g_p1t;   K = 512; use_gelu = true;  hasres = true; }
    const int N = PROJ;

    __shared__ float As[32][36];
    __shared__ float Bs[32][64];
    int bm = blockIdx.x * 32, bn = blockIdx.y * 64;
    int tid = threadIdx.x;
    int tx = tid & 15;   // cols tx*4
    int ty = tid >> 4;   // rows ty*2
    float acc[2][4];
#pragma unroll
    for (int i = 0; i < 2; i++)
#pragma unroll
        for (int j = 0; j < 4; j++) acc[i][j] = 0.f;

    for (int k0 = 0; k0 < K; k0 += 32) {
        {
            int m = tid >> 3, k4 = (tid & 7) << 2;
            float4 v = *(const float4*)&A[(bm + m) * K + k0 + k4];
            if (use_gelu) {
                v.x = gelu_exact(v.x);
                v.y = gelu_exact(v.y);
                v.z = gelu_exact(v.z);
                v.w = gelu_exact(v.w);
            }
            *(float4*)&As[m][k4] = v;
        }
#pragma unroll
        for (int t = tid; t < 512; t += 256) {
            int k = t >> 4, n4 = (t & 15) << 2;
            *(float4*)&Bs[k][n4] = *(const float4*)&B[(k0 + k) * N + bn + n4];
        }
        __syncthreads();
#pragma unroll
        for (int k = 0; k < 32; k++) {
            float a0 = As[ty * 2 + 0][k];
            float a1 = As[ty * 2 + 1][k];
            float4 b = *(float4*)&Bs[k][tx * 4];
            acc[0][0] = fmaf(a0, b.x, acc[0][0]);
            acc[0][1] = fmaf(a0, b.y, acc[0][1]);
            acc[0][2] = fmaf(a0, b.z, acc[0][2]);
            acc[0][3] = fmaf(a0, b.w, acc[0][3]);
            acc[1][0] = fmaf(a1, b.x, acc[1][0]);
            acc[1][1] = fmaf(a1, b.y, acc[1][1]);
            acc[1][2] = fmaf(a1, b.z, acc[1][2]);
            acc[1][3] = fmaf(a1, b.w, acc[1][3]);
        }
        __syncthreads();
    }
#pragma unroll
    for (int i = 0; i < 2; i++) {
        int row = bm + ty * 2 + i, col = bn + tx * 4;
        float4 bv = *(const float4*)&bias[col];
        float4 o = make_float4(acc[i][0] + bv.x, acc[i][1] + bv.y,
                               acc[i][2] + bv.z, acc[i][3] + bv.w);
        if (hasres) {
            float4 r = *(const float4*)&res[row * N + col];
            o.x += r.x; o.y += r.y; o.z += r.z; o.w += r.w;
        }
        *(float4*)&C[row * N + col] = o;
    }
}

// ---------------- fused LayerNorm(512) + classifier + log_softmax ---------
__global__ void ln_cls_k(const float* __restrict__ g_gamma, const float* __restrict__ g_beta,
                         const float* __restrict__ t_gamma, const float* __restrict__ t_beta,
                         const float* __restrict__ g_W, const float* __restrict__ g_b,
                         const float* __restrict__ t_W, const float* __restrict__ t_b,
                         float* __restrict__ out) {
    int rowg = blockIdx.x;
    int which = rowg >> 8;      // 0 = graph, 1 = text
    int row = rowg & 255;
    const float* X = which ? g_h2t : g_h2g;
    const float* gamma = which ? t_gamma : g_gamma;
    const float* beta  = which ? t_beta  : g_beta;
    const float* Wc    = which ? t_W : g_W;
    const float* bc    = which ? t_b : g_b;
    float* proj = out + which * (N_GRAPHS * PROJ) + row * PROJ;
    float* logp = out + 2 * (N_GRAPHS * PROJ) + which * (N_GRAPHS * N_CLS) + row * N_CLS;

    int tid = threadIdx.x;  // 128 threads, 4 elems each
    float4 v = *(const float4*)&X[row * 512 + tid * 4];
    float s = v.x + v.y + v.z + v.w;
    float q = v.x * v.x + v.y * v.y + v.z * v.z + v.w * v.w;
#pragma unroll
    for (int o = 16; o > 0; o >>= 1) {
        s += __shfl_xor_sync(0xffffffffu, s, o);
        q += __shfl_xor_sync(0xffffffffu, q, o);
    }
    __shared__ float ss[4], qq[4];
    __shared__ float srow[512];
    __shared__ float part[4][32];
    int warp = tid >> 5, lane = tid & 31;
    if (lane == 0) { ss[warp] = s; qq[warp] = q; }
    __syncthreads();
    s = ss[0] + ss[1] + ss[2] + ss[3];
    q = qq[0] + qq[1] + qq[2] + qq[3];
    float mean = s * (1.0f / 512.0f);
    float var = q * (1.0f / 512.0f) - mean * mean;
    float istd = rsqrtf(var + 1e-5f);
    float4 g4 = *(const float4*)&gamma[tid * 4];
    float4 b4 = *(const float4*)&beta[tid * 4];
    float4 o;
    o.x = (v.x - mean) * istd * g4.x + b4.x;
    o.y = (v.y - mean) * istd * g4.y + b4.y;
    o.z = (v.z - mean) * istd * g4.z + b4.z;
    o.w = (v.w - mean) * istd * g4.w + b4.w;
    *(float4*)&proj[tid * 4] = o;
    *(float4*)&srow[tid * 4] = o;
    __syncthreads();

    // classifier: quarter = warp, class = lane
    int c = lane;
    float acc = 0.f;
    const float* wp = Wc + (warp * 128) * 32 + c;
    const float* rp = srow + warp * 128;
#pragma unroll 8
    for (int k = 0; k < 128; k++) acc = fmaf(rp[k], wp[k * 32], acc);
    part[warp][c] = acc;
    __syncthreads();
    if (tid < 32) {
        float l = part[0][tid] + part[1][tid] + part[2][tid] + part[3][tid] + bc[tid];
        float mx = l;
#pragma unroll
        for (int o2 = 16; o2 > 0; o2 >>= 1)
            mx = fmaxf(mx, __shfl_xor_sync(0xffffffffu, mx, o2));
        float lm = l - mx;
        float ex = __expf(lm);
        float sm = ex;
#pragma unroll
        for (int o2 = 16; o2 > 0; o2 >>= 1)
            sm += __shfl_xor_sync(0xffffffffu, sm, o2);
        logp[tid] = lm - logf(sm);
    }
}

// ---------------- launch ---------------------------------------------------
extern "C" void kernel_launch(void* const* d_in, const int* in_sizes, int n_in,
                              void* d_out, int out_size) {
    const float* x       = (const float*)d_in[0];
    const int*   ei      = (const int*)d_in[1];
    const int*   src     = ei;
    const int*   dst     = ei + N_EDGES;
    const int*   batch   = (const int*)d_in[2];
    const float* text    = (const float*)d_in[3];
    const float* gcn_W   = (const float*)d_in[4];
    const float* gcn_b   = (const float*)d_in[5];
    const float* bn_g    = (const float*)d_in[6];
    const float* bn_b    = (const float*)d_in[7];
    const float* gpj_W1  = (const float*)d_in[8];
    const float* gpj_b1  = (const float*)d_in[9];
    const float* gpj_W2  = (const float*)d_in[10];
    const float* gpj_b2  = (const float*)d_in[11];
    const float* gpj_g   = (const float*)d_in[12];
    const float* gpj_be  = (const float*)d_in[13];
    const float* gcl_W   = (const float*)d_in[14];
    const float* gcl_b   = (const float*)d_in[15];
    const float* tpj_W1  = (const float*)d_in[16];
    const float* tpj_b1  = (const float*)d_in[17];
    const float* tpj_W2  = (const float*)d_in[18];
    const float* tpj_b2  = (const float*)d_in[19];
    const float* tpj_g   = (const float*)d_in[20];
    const float* tpj_be  = (const float*)d_in[21];
    const float* tcl_W   = (const float*)d_in[22];
    const float* tcl_b   = (const float*)d_in[23];
    float* out = (float*)d_out;

    // one-time host-side setup (no device memory)
    static cudaStream_t side = nullptr;
    static cudaEvent_t ev_fork, ev_gemm0, ev_text;
    if (!side) {
        cudaStreamCreateWithFlags(&side, cudaStreamNonBlocking);
        cudaEventCreateWithFlags(&ev_fork, cudaEventDisableTiming);
        cudaEventCreateWithFlags(&ev_gemm0, cudaEventDisableTiming);
        cudaEventCreateWithFlags(&ev_text, cudaEventDisableTiming);
        cudaFuncSetAttribute(gemm_node_mma_k,
                             cudaFuncAttributeMaxDynamicSharedMemorySize, GEMM_SMEM);
    }

    // ---- fork: side stream runs gemm L0 (needs only x) and the text head
    //      (needs only text) concurrently with the CSR build / GCN loop ----
    cudaEventRecord(ev_fork, 0);
    cudaStreamWaitEvent(side, ev_fork, 0);

    zero_cnt_k<<<196, 256>>>();                                   // main #1
    deg_count_k<<<(N_EDGES + 255) / 256, 256>>>(dst);             // main #2
    scan_part_k<<<196, 256>>>();                                  // main #3 (+dnorm)
    gemm_node_mma_k<<<(N_NODES + 63) / 64, 256, GEMM_SMEM, side>>>(
        x, 1, gcn_W, nullptr, nullptr, 0, 0);                     // side: L0 gemm
    cudaEventRecord(ev_gemm0, side);
    // text head on side (independent of everything until ln_cls)
    dim3 hgrid(N_GRAPHS / 32, PROJ / 64);
    gemm_head_k<<<hgrid, 256, 0, side>>>(2, text, tpj_W1, tpj_b1);
    gemm_head_k<<<hgrid, 256, 0, side>>>(3, nullptr, tpj_W2, tpj_b2);
    cudaEventRecord(ev_text, side);

    scan_add_k<<<196, 256>>>();                                   // main #4
    scatter_k<<<(N_EDGES + 255) / 256, 256>>>(src, dst);          // main #5

    // ---- GCN loop: agg l -> stats buf[l&1]; gemm l reads buf[(l-1)&1] ----
    cudaStreamWaitEvent(0, ev_gemm0, 0);
    agg_k<<<N_NODES / 8, 256>>>(gcn_b, 0);                        // layer 0 agg
    for (int l = 1; l < 4; l++) {
        gemm_node_mma_k<<<(N_NODES + 63) / 64, 256, GEMM_SMEM>>>(
            g_hbuf, 0, gcn_W + l * 128 * 128,
            bn_g + (l - 1) * 128, bn_b + (l - 1) * 128,
            (l - 1) & 1, l & 1);
        agg_k<<<N_NODES / 8, 256>>>(gcn_b + l * 128, l & 1);
    }

    // ---- pool (computes + applies final BN affine, stats buf[1]) ----
    pool_k<<<N_GRAPHS, 128>>>(batch, bn_g + 3 * 128, bn_b + 3 * 128, 1);

    // ---- graph head ----
    gemm_head_k<<<hgrid, 256>>>(0, nullptr, gpj_W1, gpj_b1);
    gemm_head_k<<<hgrid, 256>>>(1, nullptr, gpj_W2, gpj_b2);

    // ---- join text branch, then fused LN + classifier + log_softmax ----
    cudaStreamWaitEvent(0, ev_text, 0);
    ln_cls_k<<<2 * N_GRAPHS, 128>>>(gpj_g, gpj_be, tpj_g, tpj_be,
                                    gcl_W, gcl_b, tcl_W, tcl_b, out);
}

// round 15
// speedup vs baseline: 1.2573x; 1.0124x over previous
#include <cuda_runtime.h>
#include <cuda_bf16.h>
#include <math.h>

#define N_NODES  50000
#define N_EDGES  800000
#define HID      128
#define PROJ     512
#define N_CLS    32
#define N_GRAPHS 256
#define T_EMB    768

// programmatic dependent launch controls (no-ops when launched without PDL)
#define GDC_LAUNCH() asm volatile("griddepcontrol.launch_dependents;" ::: "memory")
#define GDC_WAIT()   asm volatile("griddepcontrol.wait;" ::: "memory")

// ---------------- scratch (static device globals; no runtime alloc) -------
__device__ int   g_cnt[N_NODES];
__device__ float g_dnorm[N_NODES];
__device__ int   g_rowptr[N_NODES + 1];
__device__ int   g_cursor[N_NODES];
__device__ int   g_bsum[256];
__device__ int2  g_csre[N_EDGES];   // packed {src_index, float_bits(dnorm[src])}
__device__ float g_xw[N_NODES * HID];
__device__ float g_hbuf[N_NODES * HID];
__device__ float g_stats2[2][2 * HID];   // double-buffered BN raw stats
__device__ float g_gemb[N_GRAPHS * HID];
__device__ float g_p1g[N_GRAPHS * PROJ];
__device__ float g_h2g[N_GRAPHS * PROJ];
__device__ float g_p1t[N_GRAPHS * PROJ];
__device__ float g_h2t[N_GRAPHS * PROJ];

// ---------------- small utility kernels -----------------------------------
__global__ void zero_cnt_k() {
    int i = blockIdx.x * blockDim.x + threadIdx.x;
    if (i < N_NODES) g_cnt[i] = 0;
    if (i < 2 * HID) { g_stats2[0][i] = 0.f; g_stats2[1][i] = 0.f; }
    if (i == 0) g_rowptr[N_NODES] = N_EDGES;
}

__global__ void deg_count_k(const int* __restrict__ dst) {
    int e = blockIdx.x * blockDim.x + threadIdx.x;
    if (e < N_EDGES) atomicAdd(&g_cnt[dst[e]], 1);
}

// block-level exclusive scan (196 blocks x 256 covers 50000); also dnorm.
__global__ void scan_part_k() {
    __shared__ int sh[256];
    int b = blockIdx.x, t = threadIdx.x;
    int idx = b * 256 + t;
    int v = (idx < N_NODES) ? g_cnt[idx] : 0;
    if (idx < N_NODES) g_dnorm[idx] = rsqrtf((float)v + 1.0f);
    sh[t] = v;
    __syncthreads();
    for (int o = 1; o < 256; o <<= 1) {
        int add = (t >= o) ? sh[t - o] : 0;
        __syncthreads();
        sh[t] += add;
        __syncthreads();
    }
    if (idx < N_NODES) g_rowptr[idx] = sh[t] - v;
    if (t == 255) g_bsum[b] = sh[255];
}

// adds the block-prefix of g_bsum (computed in-block) and inits cursors.
__global__ void scan_add_k() {
    __shared__ int sh[256];
    int b = blockIdx.x, t = threadIdx.x;
    sh[t] = (t < b) ? g_bsum[t] : 0;
    __syncthreads();
    for (int o = 128; o > 0; o >>= 1) {
        if (t < o) sh[t] += sh[t + o];
        __syncthreads();
    }
    int boff = sh[0];
    int idx = b * 256 + t;
    if (idx < N_NODES) {
        int rp = g_rowptr[idx] + boff;
        g_rowptr[idx] = rp;
        g_cursor[idx] = rp;
    }
}

__global__ void scatter_k(const int* __restrict__ src, const int* __restrict__ dst) {
    int e = blockIdx.x * blockDim.x + threadIdx.x;
    if (e < N_EDGES) {
        int s = src[e], d = dst[e];
        int pos = atomicAdd(&g_cursor[d], 1);
        g_csre[pos] = make_int2(s, __float_as_int(g_dnorm[s]));
    }
}

// ---------------- bf16 split helpers ---------------------------------------
__device__ __forceinline__ unsigned pack_bf16x2(float e0, float e1) {
    unsigned r;
    asm("cvt.rn.bf16x2.f32 %0, %1, %2;" : "=r"(r) : "f"(e1), "f"(e0));
    return r;
}
// split a float pair into (hi bf16x2, lo bf16x2); bf16->f32 is an exact shift.
__device__ __forceinline__ void split_pair(float e0, float e1,
                                           unsigned& hi, unsigned& lo) {
    hi = pack_bf16x2(e0, e1);
    float h0 = __uint_as_float(hi << 16);
    float h1 = __uint_as_float(hi & 0xffff0000u);
    lo = pack_bf16x2(e0 - h0, e1 - h1);
}

__device__ __forceinline__ void mma_bf16(float c[4], const unsigned a[4],
                                         unsigned b0, unsigned b1) {
    asm volatile(
        "mma.sync.aligned.m16n8k16.row.col.f32.bf16.bf16.f32 "
        "{%0,%1,%2,%3}, {%4,%5,%6,%7}, {%8,%9}, {%0,%1,%2,%3};"
        : "+f"(c[0]), "+f"(c[1]), "+f"(c[2]), "+f"(c[3])
        : "r"(a[0]), "r"(a[1]), "r"(a[2]), "r"(a[3]), "r"(b0), "r"(b1));
}

// ---------------- node GEMM via 3-term bf16 tensor cores -------------------
// C[64 x 128] per block; A tile and full W (K=128) split at smem-load time
// into bf16 hi/lo k-pair-packed u32 (separate arrays, scalar LDS mainloop).
// PDL: the W prologue (inputs only) runs BEFORE griddepcontrol.wait, so it
// overlaps the predecessor agg's tail; BN-coef read + A load come after.
// D = Ah*Wh + Ah*Wl + Al*Wh  (error ~2^-17, far under tolerance).
#define SA_STRIDE 68     // u32 stride, j-dim 64 + pad (mod 32 == 4)
#define SW_STRIDE 136    // u32 stride, n-dim 128 + pad (mod 32 == 8)
#define A_WORDS (64 * SA_STRIDE)
#define W_WORDS (64 * SW_STRIDE)
#define GEMM_SMEM ((2 * A_WORDS + 2 * W_WORDS) * 4)

__global__ __launch_bounds__(256) void gemm_node_mma_k(const float* __restrict__ xext,
                                                       int layer0,
                                                       const float* __restrict__ W,
                                                       const float* __restrict__ gamma,
                                                       const float* __restrict__ beta,
                                                       int rb, int zb) {
    extern __shared__ unsigned smem_u[];
    unsigned* sAhi = smem_u;                       // [64 rows][68]  (j = k/2)
    unsigned* sAlo = smem_u + A_WORDS;
    unsigned* sWhi = smem_u + 2 * A_WORDS;         // [64 j][136 n]
    unsigned* sWlo = smem_u + 2 * A_WORDS + W_WORDS;
    const float* A = layer0 ? xext : g_hbuf;
    int bm = blockIdx.x * 64;
    int tid = threadIdx.x;

    GDC_LAUNCH();   // let the dependent (next agg) launch its prologue early

    // ---- pre-wait phase: W load+split (reads only kernel inputs) ----
#pragma unroll
    for (int i = 0; i < 8; i++) {
        int t = tid + i * 256;           // 2048 (j, n4) slots
        int j = t >> 5, n4 = (t & 31) << 2;
        float4 w0 = *(const float4*)&W[(2 * j) * 128 + n4];
        float4 w1 = *(const float4*)&W[(2 * j + 1) * 128 + n4];
        uint4 hi, lo;
        split_pair(w0.x, w1.x, hi.x, lo.x);
        split_pair(w0.y, w1.y, hi.y, lo.y);
        split_pair(w0.z, w1.z, hi.z, lo.z);
        split_pair(w0.w, w1.w, hi.w, lo.w);
        int off = j * SW_STRIDE + n4;
        *(uint4*)&sWhi[off] = hi;
        *(uint4*)&sWlo[off] = lo;
    }

    GDC_WAIT();     // predecessor (agg) outputs now complete + visible

    // per-thread BN coefs for the 4 channels this thread loads
    float scj[4] = {0.f, 0.f, 0.f, 0.f}, shj[4] = {0.f, 0.f, 0.f, 0.f};
    if (!layer0) {
        int c0 = (tid & 31) << 2;
        const float inv = 1.0f / (float)N_NODES;
#pragma unroll
        for (int j = 0; j < 4; j++) {
            float mu = g_stats2[rb][c0 + j] * inv;
            float var = g_stats2[rb][HID + c0 + j] * inv - mu * mu;
            float sc = rsqrtf(var + 1e-5f) * gamma[c0 + j];
            scj[j] = sc;
            shj[j] = beta[c0 + j] - mu * sc;
        }
        if (tid < 2 * HID) g_stats2[zb][tid] = 0.f;  // idempotent reset
    }

    // load A tile (64 rows x 128 k), BN affine fused, split into bf16 hi/lo
#pragma unroll
    for (int i = 0; i < 8; i++) {
        int t = tid + i * 256;           // 2048 float4 slots
        int r = t >> 5, c4 = (t & 31) << 2;   // k start (multiple of 4)
        int row = bm + r;
        float4 v = make_float4(0.f, 0.f, 0.f, 0.f);
        if (row < N_NODES) v = *(const float4*)&A[row * 128 + c4];
        if (!layer0) {
            v.x = fmaf(v.x, scj[0], shj[0]);
            v.y = fmaf(v.y, scj[1], shj[1]);
            v.z = fmaf(v.z, scj[2], shj[2]);
            v.w = fmaf(v.w, scj[3], shj[3]);
        }
        uint2 hi, lo;
        split_pair(v.x, v.y, hi.x, lo.x);
        split_pair(v.z, v.w, hi.y, lo.y);
        int joff = r * SA_STRIDE + (c4 >> 1);
        *(uint2*)&sAhi[joff] = hi;
        *(uint2*)&sAlo[joff] = lo;
    }
    __syncthreads();

    int w = tid >> 5, lane = tid & 31;
    int g = lane >> 2, tig = lane & 3;
    int r0 = (w & 3) * 16;       // warp row base within tile
    int bn = (w >> 2) * 64;      // warp col base

    float c[8][4];
#pragma unroll
    for (int t = 0; t < 8; t++)
#pragma unroll
        for (int j = 0; j < 4; j++) c[t][j] = 0.f;

#pragma unroll
    for (int ks = 0; ks < 8; ks++) {       // k16 per step, K=128
        int jb = ks * 8;                   // j = k/2 base
        unsigned ahi[4], alo[4];
        int aoff0 = (r0 + g) * SA_STRIDE + jb + tig;
        int aoff1 = (r0 + g + 8) * SA_STRIDE + jb + tig;
        ahi[0] = sAhi[aoff0];
        ahi[1] = sAhi[aoff1];
        ahi[2] = sAhi[aoff0 + 4];
        ahi[3] = sAhi[aoff1 + 4];
        alo[0] = sAlo[aoff0];
        alo[1] = sAlo[aoff1];
        alo[2] = sAlo[aoff0 + 4];
        alo[3] = sAlo[aoff1 + 4];
#pragma unroll
        for (int t = 0; t < 8; t++) {
            int n = bn + t * 8 + g;
            int woff0 = (jb + tig) * SW_STRIDE + n;
            int woff1 = (jb + tig + 4) * SW_STRIDE + n;
            unsigned whi0 = sWhi[woff0];
            unsigned whi1 = sWhi[woff1];
            unsigned wlo0 = sWlo[woff0];
            unsigned wlo1 = sWlo[woff1];
            mma_bf16(c[t], ahi, whi0, whi1);
            mma_bf16(c[t], ahi, wlo0, wlo1);
            mma_bf16(c[t], alo, whi0, whi1);
        }
    }

    // epilogue: c0,c1 -> row g, cols tig*2, tig*2+1 ; c2,c3 -> row g+8
#pragma unroll
    for (int t = 0; t < 8; t++) {
        int n0 = bn + t * 8 + tig * 2;
        int row = bm + r0 + g;
        if (row < N_NODES)
            *(float2*)&g_xw[row * 128 + n0] = make_float2(c[t][0], c[t][1]);
        if (row + 8 < N_NODES)
            *(float2*)&g_xw[(row + 8) * 128 + n0] = make_float2(c[t][2], c[t][3]);
    }
}

// ---------------- aggregation + bias + leaky relu + BN stats --------------
__global__ __launch_bounds__(256) void agg_k(const float* __restrict__ bias, int sb) {
    __shared__ float s_sum[HID];
    __shared__ float s_sq[HID];
    int tid = threadIdx.x;
    GDC_LAUNCH();   // let the dependent (next gemm) run its W prologue early
    if (tid < HID) { s_sum[tid] = 0.f; s_sq[tid] = 0.f; }
    GDC_WAIT();     // predecessor (gemm / scatter) outputs complete
    __syncthreads();

    int node = blockIdx.x * 8 + (tid >> 5);  // 6250 blocks * 8 warps == 50000
    int lane = tid & 31;
    float dn = g_dnorm[node];
    const float4* base = (const float4*)g_xw;
    float4 self = base[node * 32 + lane];
    float4 a0 = make_float4(0.f, 0.f, 0.f, 0.f);
    float4 a1 = make_float4(0.f, 0.f, 0.f, 0.f);
    float4 a2 = make_float4(0.f, 0.f, 0.f, 0.f);
    float4 a3 = make_float4(0.f, 0.f, 0.f, 0.f);
    int s = g_rowptr[node], e = g_rowptr[node + 1];
    int i = s;
    for (; i + 3 < e; i += 4) {
        int2 c0 = g_csre[i];
        int2 c1 = g_csre[i + 1];
        int2 c2 = g_csre[i + 2];
        int2 c3 = g_csre[i + 3];
        float4 u0 = base[c0.x * 32 + lane];
        float4 u1 = base[c1.x * 32 + lane];
        float4 u2 = base[c2.x * 32 + lane];
        float4 u3 = base[c3.x * 32 + lane];
        float w0 = __int_as_float(c0.y);
        float w1 = __int_as_float(c1.y);
        float w2 = __int_as_float(c2.y);
        float w3 = __int_as_float(c3.y);
        a0.x = fmaf(w0, u0.x, a0.x); a0.y = fmaf(w0, u0.y, a0.y);
        a0.z = fmaf(w0, u0.z, a0.z); a0.w = fmaf(w0, u0.w, a0.w);
        a1.x = fmaf(w1, u1.x, a1.x); a1.y = fmaf(w1, u1.y, a1.y);
        a1.z = fmaf(w1, u1.z, a1.z); a1.w = fmaf(w1, u1.w, a1.w);
        a2.x = fmaf(w2, u2.x, a2.x); a2.y = fmaf(w2, u2.y, a2.y);
        a2.z = fmaf(w2, u2.z, a2.z); a2.w = fmaf(w2, u2.w, a2.w);
        a3.x = fmaf(w3, u3.x, a3.x); a3.y = fmaf(w3, u3.y, a3.y);
        a3.z = fmaf(w3, u3.z, a3.z); a3.w = fmaf(w3, u3.w, a3.w);
    }
    for (; i < e; i++) {
        int2 cc = g_csre[i];
        float ww = __int_as_float(cc.y);
        float4 u = base[cc.x * 32 + lane];
        a0.x = fmaf(ww, u.x, a0.x); a0.y = fmaf(ww, u.y, a0.y);
        a0.z = fmaf(ww, u.z, a0.z); a0.w = fmaf(ww, u.w, a0.w);
    }
    float4 acc;
    acc.x = (a0.x + a1.x) + (a2.x + a3.x);
    acc.y = (a0.y + a1.y) + (a2.y + a3.y);
    acc.z = (a0.z + a1.z) + (a2.z + a3.z);
    acc.w = (a0.w + a1.w) + (a2.w + a3.w);

    float4 bv = *(const float4*)&bias[lane * 4];
    float dn2 = dn * dn;
    float4 y;
    y.x = dn * acc.x + dn2 * self.x + bv.x;
    y.y = dn * acc.y + dn2 * self.y + bv.y;
    y.z = dn * acc.z + dn2 * self.z + bv.z;
    y.w = dn * acc.w + dn2 * self.w + bv.w;
    // leaky relu 0.01
    y.x = y.x > 0.f ? y.x : 0.01f * y.x;
    y.y = y.y > 0.f ? y.y : 0.01f * y.y;
    y.z = y.z > 0.f ? y.z : 0.01f * y.z;
    y.w = y.w > 0.f ? y.w : 0.01f * y.w;
    *(float4*)&g_hbuf[node * 128 + lane * 4] = y;

    int c = lane * 4;
    atomicAdd(&s_sum[c + 0], y.x);
    atomicAdd(&s_sum[c + 1], y.y);
    atomicAdd(&s_sum[c + 2], y.z);
    atomicAdd(&s_sum[c + 3], y.w);
    atomicAdd(&s_sq[c + 0], y.x * y.x);
    atomicAdd(&s_sq[c + 1], y.y * y.y);
    atomicAdd(&s_sq[c + 2], y.z * y.z);
    atomicAdd(&s_sq[c + 3], y.w * y.w);
    __syncthreads();
    if (tid < HID) {
        atomicAdd(&g_stats2[sb][tid], s_sum[tid]);
        atomicAdd(&g_stats2[sb][HID + tid], s_sq[tid]);
    }
}

// ---------------- mean pool (binary search on sorted batch) ---------------
__device__ __forceinline__ int lower_bound_dev(const int* a, int n, int v) {
    int lo = 0, hi = n;
    while (lo < hi) {
        int m = (lo + hi) >> 1;
        if (a[m] < v) lo = m + 1; else hi = m;
    }
    return lo;
}

__global__ void pool_k(const int* __restrict__ batch,
                       const float* __restrict__ gamma,
                       const float* __restrict__ beta, int sb) {
    GDC_LAUNCH();
    GDC_WAIT();
    int g = blockIdx.x;
    __shared__ int se[2];
    if (threadIdx.x == 0) {
        se[0] = lower_bound_dev(batch, N_NODES, g);
        se[1] = lower_bound_dev(batch, N_NODES, g + 1);
    }
    __syncthreads();
    int s = se[0], e = se[1];
    int c = threadIdx.x;  // 128 threads
    const float inv = 1.0f / (float)N_NODES;
    float mu = g_stats2[sb][c] * inv;
    float var = g_stats2[sb][HID + c] * inv - mu * mu;
    float sc = rsqrtf(var + 1e-5f) * gamma[c];
    float sh = beta[c] - mu * sc;
    float acc = 0.f;
    for (int i = s; i < e; i++) acc += g_hbuf[i * 128 + c];
    float n = (float)(e - s);
    float cnt = fmaxf(n, 1.0f);
    g_gemb[g * 128 + c] = (sc * acc + sh * n) / cnt;
}

// ---------------- head GEMM (M=256, N=512, K in {128,512,768}) ------------
__device__ __forceinline__ float gelu_exact(float x) {
    return 0.5f * x * (1.0f + erff(x * 0.70710678118654752f));
}

__global__ __launch_bounds__(256) void gemm_head_k(int which,
                                                   const float* __restrict__ Aext,
                                                   const float* __restrict__ B,
                                                   const float* __restrict__ bias) {
    const float* A;
    float* C;
    const float* res;
    int K;
    bool use_gelu, hasres;
    if (which == 0)      { A = g_gemb; C = g_p1g; res = nullptr; K = 128; use_gelu = false; hasres = false; }
    else if (which == 1) { A = g_p1g;  C = g_h2g; res = g_p1g;   K = 512; use_gelu = true;  hasres = true; }
    else if (which == 2) { A = Aext;   C = g_p1t; res = nullptr; K = 768; use_gelu = false; hasres = false; }
    else                 { A = g_p1t;  C = g_h2t; res = g_p1t;   K = 512; use_gelu = true;  hasres = true; }
    const int N = PROJ;

    __shared__ float As[32][36];
    __shared__ float Bs[32][64];
    int bm = blockIdx.x * 32, bn = blockIdx.y * 64;
    int tid = threadIdx.x;
    int tx = tid & 15;   // cols tx*4
    int ty = tid >> 4;   // rows ty*2
    float acc[2][4];
#pragma unroll
    for (int i = 0; i < 2; i++)
#pragma unroll
        for (int j = 0; j < 4; j++) acc[i][j] = 0.f;

    for (int k0 = 0; k0 < K; k0 += 32) {
        {
            int m = tid >> 3, k4 = (tid & 7) << 2;
            float4 v = *(const float4*)&A[(bm + m) * K + k0 + k4];
            if (use_gelu) {
                v.x = gelu_exact(v.x);
                v.y = gelu_exact(v.y);
                v.z = gelu_exact(v.z);
                v.w = gelu_exact(v.w);
            }
            *(float4*)&As[m][k4] = v;
        }
#pragma unroll
        for (int t = tid; t < 512; t += 256) {
            int k = t >> 4, n4 = (t & 15) << 2;
            *(float4*)&Bs[k][n4] = *(const float4*)&B[(k0 + k) * N + bn + n4];
        }
        __syncthreads();
#pragma unroll
        for (int k = 0; k < 32; k++) {
            float a0 = As[ty * 2 + 0][k];
            float a1 = As[ty * 2 + 1][k];
            float4 b = *(float4*)&Bs[k][tx * 4];
            acc[0][0] = fmaf(a0, b.x, acc[0][0]);
            acc[0][1] = fmaf(a0, b.y, acc[0][1]);
            acc[0][2] = fmaf(a0, b.z, acc[0][2]);
            acc[0][3] = fmaf(a0, b.w, acc[0][3]);
            acc[1][0] = fmaf(a1, b.x, acc[1][0]);
            acc[1][1] = fmaf(a1, b.y, acc[1][1]);
            acc[1][2] = fmaf(a1, b.z, acc[1][2]);
            acc[1][3] = fmaf(a1, b.w, acc[1][3]);
        }
        __syncthreads();
    }
#pragma unroll
    for (int i = 0; i < 2; i++) {
        int row = bm + ty * 2 + i, col = bn + tx * 4;
        float4 bv = *(const float4*)&bias[col];
        float4 o = make_float4(acc[i][0] + bv.x, acc[i][1] + bv.y,
                               acc[i][2] + bv.z, acc[i][3] + bv.w);
        if (hasres) {
            float4 r = *(const float4*)&res[row * N + col];
            o.x += r.x; o.y += r.y; o.z += r.z; o.w += r.w;
        }
        *(float4*)&C[row * N + col] = o;
    }
}

// ---------------- fused LayerNorm(512) + classifier + log_softmax ---------
__global__ void ln_cls_k(const float* __restrict__ g_gamma, const float* __restrict__ g_beta,
                         const float* __restrict__ t_gamma, const float* __restrict__ t_beta,
                         const float* __restrict__ g_W, const float* __restrict__ g_b,
                         const float* __restrict__ t_W, const float* __restrict__ t_b,
                         float* __restrict__ out) {
    int rowg = blockIdx.x;
    int which = rowg >> 8;      // 0 = graph, 1 = text
    int row = rowg & 255;
    const float* X = which ? g_h2t : g_h2g;
    const float* gamma = which ? t_gamma : g_gamma;
    const float* beta  = which ? t_beta  : g_beta;
    const float* Wc    = which ? t_W : g_W;
    const float* bc    = which ? t_b : g_b;
    float* proj = out + which * (N_GRAPHS * PROJ) + row * PROJ;
    float* logp = out + 2 * (N_GRAPHS * PROJ) + which * (N_GRAPHS * N_CLS) + row * N_CLS;

    int tid = threadIdx.x;  // 128 threads, 4 elems each
    float4 v = *(const float4*)&X[row * 512 + tid * 4];
    float s = v.x + v.y + v.z + v.w;
    float q = v.x * v.x + v.y * v.y + v.z * v.z + v.w * v.w;
#pragma unroll
    for (int o = 16; o > 0; o >>= 1) {
        s += __shfl_xor_sync(0xffffffffu, s, o);
        q += __shfl_xor_sync(0xffffffffu, q, o);
    }
    __shared__ float ss[4], qq[4];
    __shared__ float srow[512];
    __shared__ float part[4][32];
    int warp = tid >> 5, lane = tid & 31;
    if (lane == 0) { ss[warp] = s; qq[warp] = q; }
    __syncthreads();
    s = ss[0] + ss[1] + ss[2] + ss[3];
    q = qq[0] + qq[1] + qq[2] + qq[3];
    float mean = s * (1.0f / 512.0f);
    float var = q * (1.0f / 512.0f) - mean * mean;
    float istd = rsqrtf(var + 1e-5f);
    float4 g4 = *(const float4*)&gamma[tid * 4];
    float4 b4 = *(const float4*)&beta[tid * 4];
    float4 o;
    o.x = (v.x - mean) * istd * g4.x + b4.x;
    o.y = (v.y - mean) * istd * g4.y + b4.y;
    o.z = (v.z - mean) * istd * g4.z + b4.z;
    o.w = (v.w - mean) * istd * g4.w + b4.w;
    *(float4*)&proj[tid * 4] = o;
    *(float4*)&srow[tid * 4] = o;
    __syncthreads();

    // classifier: quarter = warp, class = lane
    int c = lane;
    float acc = 0.f;
    const float* wp = Wc + (warp * 128) * 32 + c;
    const float* rp = srow + warp * 128;
#pragma unroll 8
    for (int k = 0; k < 128; k++) acc = fmaf(rp[k], wp[k * 32], acc);
    part[warp][c] = acc;
    __syncthreads();
    if (tid < 32) {
        float l = part[0][tid] + part[1][tid] + part[2][tid] + part[3][tid] + bc[tid];
        float mx = l;
#pragma unroll
        for (int o2 = 16; o2 > 0; o2 >>= 1)
            mx = fmaxf(mx, __shfl_xor_sync(0xffffffffu, mx, o2));
        float lm = l - mx;
        float ex = __expf(lm);
        float sm = ex;
#pragma unroll
        for (int o2 = 16; o2 > 0; o2 >>= 1)
            sm += __shfl_xor_sync(0xffffffffu, sm, o2);
        logp[tid] = lm - logf(sm);
    }
}

// ---------------- launch ---------------------------------------------------
extern "C" void kernel_launch(void* const* d_in, const int* in_sizes, int n_in,
                              void* d_out, int out_size) {
    const float* x       = (const float*)d_in[0];
    const int*   ei      = (const int*)d_in[1];
    const int*   src     = ei;
    const int*   dst     = ei + N_EDGES;
    const int*   batch   = (const int*)d_in[2];
    const float* text    = (const float*)d_in[3];
    const float* gcn_W   = (const float*)d_in[4];
    const float* gcn_b   = (const float*)d_in[5];
    const float* bn_g    = (const float*)d_in[6];
    const float* bn_b    = (const float*)d_in[7];
    const float* gpj_W1  = (const float*)d_in[8];
    const float* gpj_b1  = (const float*)d_in[9];
    const float* gpj_W2  = (const float*)d_in[10];
    const float* gpj_b2  = (const float*)d_in[11];
    const float* gpj_g   = (const float*)d_in[12];
    const float* gpj_be  = (const float*)d_in[13];
    const float* gcl_W   = (const float*)d_in[14];
    const float* gcl_b   = (const float*)d_in[15];
    const float* tpj_W1  = (const float*)d_in[16];
    const float* tpj_b1  = (const float*)d_in[17];
    const float* tpj_W2  = (const float*)d_in[18];
    const float* tpj_b2  = (const float*)d_in[19];
    const float* tpj_g   = (const float*)d_in[20];
    const float* tpj_be  = (const float*)d_in[21];
    const float* tcl_W   = (const float*)d_in[22];
    const float* tcl_b   = (const float*)d_in[23];
    float* out = (float*)d_out;

    // one-time host-side setup (no device memory)
    static cudaStream_t side = nullptr;
    static cudaEvent_t ev_fork, ev_gemm0, ev_text;
    if (!side) {
        cudaStreamCreateWithFlags(&side, cudaStreamNonBlocking);
        cudaEventCreateWithFlags(&ev_fork, cudaEventDisableTiming);
        cudaEventCreateWithFlags(&ev_gemm0, cudaEventDisableTiming);
        cudaEventCreateWithFlags(&ev_text, cudaEventDisableTiming);
        cudaFuncSetAttribute(gemm_node_mma_k,
                             cudaFuncAttributeMaxDynamicSharedMemorySize, GEMM_SMEM);
    }

    // PDL launch config (default stream)
    cudaLaunchAttribute pdl_attr;
    pdl_attr.id = cudaLaunchAttributeProgrammaticStreamSerialization;
    pdl_attr.val.programmaticStreamSerializationAllowed = 1;

    // ---- fork: side stream runs gemm L0 (needs only x) and the text head
    //      (needs only text) concurrently with the CSR build / GCN loop ----
    cudaEventRecord(ev_fork, 0);
    cudaStreamWaitEvent(side, ev_fork, 0);

    zero_cnt_k<<<196, 256>>>();                                   // main #1
    deg_count_k<<<(N_EDGES + 255) / 256, 256>>>(dst);             // main #2
    scan_part_k<<<196, 256>>>();                                  // main #3 (+dnorm)
    gemm_node_mma_k<<<(N_NODES + 63) / 64, 256, GEMM_SMEM, side>>>(
        x, 1, gcn_W, (const float*)nullptr, (const float*)nullptr, 0, 0);
    cudaEventRecord(ev_gemm0, side);
    // text head on side (independent of everything until ln_cls)
    dim3 hgrid(N_GRAPHS / 32, PROJ / 64);
    gemm_head_k<<<hgrid, 256, 0, side>>>(2, text, tpj_W1, tpj_b1);
    gemm_head_k<<<hgrid, 256, 0, side>>>(3, (const float*)nullptr, tpj_W2, tpj_b2);
    cudaEventRecord(ev_text, side);

    scan_add_k<<<196, 256>>>();                                   // main #4
    scatter_k<<<(N_EDGES + 255) / 256, 256>>>(src, dst);          // main #5

    // ---- GCN loop with PDL: agg l -> stats buf[l&1]; gemm l reads
    //      buf[(l-1)&1]; each gemm's W prologue overlaps the prior agg ----
    cudaStreamWaitEvent(0, ev_gemm0, 0);
    {
        cudaLaunchConfig_t cfg = {};
        cfg.blockDim = {256, 1, 1};
        cfg.stream = 0;
        cfg.attrs = &pdl_attr;
        cfg.numAttrs = 1;

        cfg.gridDim = {N_NODES / 8, 1, 1};
        cfg.dynamicSmemBytes = 0;
        cudaLaunchKernelEx(&cfg, agg_k, gcn_b, 0);                // layer 0 agg
        for (int l = 1; l < 4; l++) {
            cfg.gridDim = {(N_NODES + 63) / 64, 1, 1};
            cfg.dynamicSmemBytes = GEMM_SMEM;
            cudaLaunchKernelEx(&cfg, gemm_node_mma_k,
                               (const float*)g_hbuf, 0,
                               (const float*)(gcn_W + l * 128 * 128),
                               (const float*)(bn_g + (l - 1) * 128),
                               (const float*)(bn_b + (l - 1) * 128),
                               (l - 1) & 1, l & 1);
            cfg.gridDim = {N_NODES / 8, 1, 1};
            cfg.dynamicSmemBytes = 0;
            cudaLaunchKernelEx(&cfg, agg_k, (const float*)(gcn_b + l * 128), l & 1);
        }

        // pool with PDL (predecessor agg3)
        cfg.gridDim = {N_GRAPHS, 1, 1};
        cfg.blockDim = {128, 1, 1};
        cfg.dynamicSmemBytes = 0;
        cudaLaunchKernelEx(&cfg, pool_k, batch,
                           (const float*)(bn_g + 3 * 128),
                           (const float*)(bn_b + 3 * 128), 1);
    }

    // ---- graph head ----
    gemm_head_k<<<hgrid, 256>>>(0, (const float*)nullptr, gpj_W1, gpj_b1);
    gemm_head_k<<<hgrid, 256>>>(1, (const float*)nullptr, gpj_W2, gpj_b2);

    // ---- join text branch, then fused LN + classifier + log_softmax ----
    cudaStreamWaitEvent(0, ev_text, 0);
    ln_cls_k<<<2 * N_GRAPHS, 128>>>(gpj_g, gpj_be, tpj_g, tpj_be,
                                    gcl_W, gcl_b, tcl_W, tcl_b, out);
}

// round 16
// speedup vs baseline: 1.2625x; 1.0041x over previous
#include <cuda_runtime.h>
#include <cuda_bf16.h>
#include <cuda_fp16.h>
#include <math.h>

#define N_NODES  50000
#define N_EDGES  800000
#define HID      128
#define PROJ     512
#define N_CLS    32
#define N_GRAPHS 256
#define T_EMB    768

// programmatic dependent launch controls (no-ops when launched without PDL)
#define GDC_LAUNCH() asm volatile("griddepcontrol.launch_dependents;" ::: "memory")
#define GDC_WAIT()   asm volatile("griddepcontrol.wait;" ::: "memory")

// ---------------- scratch (static device globals; no runtime alloc) -------
__device__ int   g_cnt[N_NODES];
__device__ float g_dnorm[N_NODES];
__device__ int   g_rowptr[N_NODES + 1];
__device__ int   g_cursor[N_NODES];
__device__ int   g_bsum[256];
__device__ int2  g_csre[N_EDGES];   // packed {src_index, float_bits(dnorm[src])}
__device__ __half2 g_xwh[N_NODES * 64];   // xw in fp16 (half L2 gather traffic)
__device__ float g_hbuf[N_NODES * HID];
__device__ float g_stats2[2][2 * HID];   // double-buffered BN raw stats
__device__ float g_gemb[N_GRAPHS * HID];
__device__ float g_p1g[N_GRAPHS * PROJ];
__device__ float g_h2g[N_GRAPHS * PROJ];
__device__ float g_p1t[N_GRAPHS * PROJ];
__device__ float g_h2t[N_GRAPHS * PROJ];

// ---------------- small utility kernels -----------------------------------
__global__ void zero_cnt_k() {
    int i = blockIdx.x * blockDim.x + threadIdx.x;
    if (i < N_NODES) g_cnt[i] = 0;
    if (i < 2 * HID) { g_stats2[0][i] = 0.f; g_stats2[1][i] = 0.f; }
    if (i == 0) g_rowptr[N_NODES] = N_EDGES;
}

__global__ void deg_count_k(const int* __restrict__ dst) {
    int e = blockIdx.x * blockDim.x + threadIdx.x;
    if (e < N_EDGES) atomicAdd(&g_cnt[dst[e]], 1);
}

// block-level exclusive scan (196 blocks x 256 covers 50000); also dnorm.
__global__ void scan_part_k() {
    __shared__ int sh[256];
    int b = blockIdx.x, t = threadIdx.x;
    int idx = b * 256 + t;
    int v = (idx < N_NODES) ? g_cnt[idx] : 0;
    if (idx < N_NODES) g_dnorm[idx] = rsqrtf((float)v + 1.0f);
    sh[t] = v;
    __syncthreads();
    for (int o = 1; o < 256; o <<= 1) {
        int add = (t >= o) ? sh[t - o] : 0;
        __syncthreads();
        sh[t] += add;
        __syncthreads();
    }
    if (idx < N_NODES) g_rowptr[idx] = sh[t] - v;
    if (t == 255) g_bsum[b] = sh[255];
}

// adds the block-prefix of g_bsum (computed in-block) and inits cursors.
__global__ void scan_add_k() {
    __shared__ int sh[256];
    int b = blockIdx.x, t = threadIdx.x;
    sh[t] = (t < b) ? g_bsum[t] : 0;
    __syncthreads();
    for (int o = 128; o > 0; o >>= 1) {
        if (t < o) sh[t] += sh[t + o];
        __syncthreads();
    }
    int boff = sh[0];
    int idx = b * 256 + t;
    if (idx < N_NODES) {
        int rp = g_rowptr[idx] + boff;
        g_rowptr[idx] = rp;
        g_cursor[idx] = rp;
    }
}

__global__ void scatter_k(const int* __restrict__ src, const int* __restrict__ dst) {
    int e = blockIdx.x * blockDim.x + threadIdx.x;
    if (e < N_EDGES) {
        int s = src[e], d = dst[e];
        int pos = atomicAdd(&g_cursor[d], 1);
        g_csre[pos] = make_int2(s, __float_as_int(g_dnorm[s]));
    }
}

// ---------------- bf16 split helpers ---------------------------------------
__device__ __forceinline__ unsigned pack_bf16x2(float e0, float e1) {
    unsigned r;
    asm("cvt.rn.bf16x2.f32 %0, %1, %2;" : "=r"(r) : "f"(e1), "f"(e0));
    return r;
}
// split a float pair into (hi bf16x2, lo bf16x2); bf16->f32 is an exact shift.
__device__ __forceinline__ void split_pair(float e0, float e1,
                                           unsigned& hi, unsigned& lo) {
    hi = pack_bf16x2(e0, e1);
    float h0 = __uint_as_float(hi << 16);
    float h1 = __uint_as_float(hi & 0xffff0000u);
    lo = pack_bf16x2(e0 - h0, e1 - h1);
}

__device__ __forceinline__ void mma_bf16(float c[4], const unsigned a[4],
                                         unsigned b0, unsigned b1) {
    asm volatile(
        "mma.sync.aligned.m16n8k16.row.col.f32.bf16.bf16.f32 "
        "{%0,%1,%2,%3}, {%4,%5,%6,%7}, {%8,%9}, {%0,%1,%2,%3};"
        : "+f"(c[0]), "+f"(c[1]), "+f"(c[2]), "+f"(c[3])
        : "r"(a[0]), "r"(a[1]), "r"(a[2]), "r"(a[3]), "r"(b0), "r"(b1));
}

// ---------------- node GEMM via 3-term bf16 tensor cores -------------------
// C[64 x 128] per block; A tile and full W (K=128) split at smem-load time
// into bf16 hi/lo k-pair-packed u32 (separate arrays, scalar LDS mainloop).
// PDL: W prologue (inputs only) runs BEFORE griddepcontrol.wait.
// Output written as fp16 (g_xwh) to halve the aggregation gather traffic.
// D = Ah*Wh + Ah*Wl + Al*Wh  (error ~2^-17); fp16 store adds ~2^-11.
#define SA_STRIDE 68     // u32 stride, j-dim 64 + pad (mod 32 == 4)
#define SW_STRIDE 136    // u32 stride, n-dim 128 + pad (mod 32 == 8)
#define A_WORDS (64 * SA_STRIDE)
#define W_WORDS (64 * SW_STRIDE)
#define GEMM_SMEM ((2 * A_WORDS + 2 * W_WORDS) * 4)

__global__ __launch_bounds__(256) void gemm_node_mma_k(const float* __restrict__ xext,
                                                       int layer0,
                                                       const float* __restrict__ W,
                                                       const float* __restrict__ gamma,
                                                       const float* __restrict__ beta,
                                                       int rb, int zb) {
    extern __shared__ unsigned smem_u[];
    unsigned* sAhi = smem_u;                       // [64 rows][68]  (j = k/2)
    unsigned* sAlo = smem_u + A_WORDS;
    unsigned* sWhi = smem_u + 2 * A_WORDS;         // [64 j][136 n]
    unsigned* sWlo = smem_u + 2 * A_WORDS + W_WORDS;
    const float* A = layer0 ? xext : g_hbuf;
    int bm = blockIdx.x * 64;
    int tid = threadIdx.x;

    GDC_LAUNCH();   // let the dependent (next agg) launch its prologue early

    // ---- pre-wait phase: W load+split (reads only kernel inputs) ----
#pragma unroll
    for (int i = 0; i < 8; i++) {
        int t = tid + i * 256;           // 2048 (j, n4) slots
        int j = t >> 5, n4 = (t & 31) << 2;
        float4 w0 = *(const float4*)&W[(2 * j) * 128 + n4];
        float4 w1 = *(const float4*)&W[(2 * j + 1) * 128 + n4];
        uint4 hi, lo;
        split_pair(w0.x, w1.x, hi.x, lo.x);
        split_pair(w0.y, w1.y, hi.y, lo.y);
        split_pair(w0.z, w1.z, hi.z, lo.z);
        split_pair(w0.w, w1.w, hi.w, lo.w);
        int off = j * SW_STRIDE + n4;
        *(uint4*)&sWhi[off] = hi;
        *(uint4*)&sWlo[off] = lo;
    }

    GDC_WAIT();     // predecessor (agg) outputs now complete + visible

    // per-thread BN coefs for the 4 channels this thread loads
    float scj[4] = {0.f, 0.f, 0.f, 0.f}, shj[4] = {0.f, 0.f, 0.f, 0.f};
    if (!layer0) {
        int c0 = (tid & 31) << 2;
        const float inv = 1.0f / (float)N_NODES;
#pragma unroll
        for (int j = 0; j < 4; j++) {
            float mu = g_stats2[rb][c0 + j] * inv;
            float var = g_stats2[rb][HID + c0 + j] * inv - mu * mu;
            float sc = rsqrtf(var + 1e-5f) * gamma[c0 + j];
            scj[j] = sc;
            shj[j] = beta[c0 + j] - mu * sc;
        }
        if (tid < 2 * HID) g_stats2[zb][tid] = 0.f;  // idempotent reset
    }

    // load A tile (64 rows x 128 k), BN affine fused, split into bf16 hi/lo
#pragma unroll
    for (int i = 0; i < 8; i++) {
        int t = tid + i * 256;           // 2048 float4 slots
        int r = t >> 5, c4 = (t & 31) << 2;   // k start (multiple of 4)
        int row = bm + r;
        float4 v = make_float4(0.f, 0.f, 0.f, 0.f);
        if (row < N_NODES) v = *(const float4*)&A[row * 128 + c4];
        if (!layer0) {
            v.x = fmaf(v.x, scj[0], shj[0]);
            v.y = fmaf(v.y, scj[1], shj[1]);
            v.z = fmaf(v.z, scj[2], shj[2]);
            v.w = fmaf(v.w, scj[3], shj[3]);
        }
        uint2 hi, lo;
        split_pair(v.x, v.y, hi.x, lo.x);
        split_pair(v.z, v.w, hi.y, lo.y);
        int joff = r * SA_STRIDE + (c4 >> 1);
        *(uint2*)&sAhi[joff] = hi;
        *(uint2*)&sAlo[joff] = lo;
    }
    __syncthreads();

    int w = tid >> 5, lane = tid & 31;
    int g = lane >> 2, tig = lane & 3;
    int r0 = (w & 3) * 16;       // warp row base within tile
    int bn = (w >> 2) * 64;      // warp col base

    float c[8][4];
#pragma unroll
    for (int t = 0; t < 8; t++)
#pragma unroll
        for (int j = 0; j < 4; j++) c[t][j] = 0.f;

#pragma unroll
    for (int ks = 0; ks < 8; ks++) {       // k16 per step, K=128
        int jb = ks * 8;                   // j = k/2 base
        unsigned ahi[4], alo[4];
        int aoff0 = (r0 + g) * SA_STRIDE + jb + tig;
        int aoff1 = (r0 + g + 8) * SA_STRIDE + jb + tig;
        ahi[0] = sAhi[aoff0];
        ahi[1] = sAhi[aoff1];
        ahi[2] = sAhi[aoff0 + 4];
        ahi[3] = sAhi[aoff1 + 4];
        alo[0] = sAlo[aoff0];
        alo[1] = sAlo[aoff1];
        alo[2] = sAlo[aoff0 + 4];
        alo[3] = sAlo[aoff1 + 4];
#pragma unroll
        for (int t = 0; t < 8; t++) {
            int n = bn + t * 8 + g;
            int woff0 = (jb + tig) * SW_STRIDE + n;
            int woff1 = (jb + tig + 4) * SW_STRIDE + n;
            unsigned whi0 = sWhi[woff0];
            unsigned whi1 = sWhi[woff1];
            unsigned wlo0 = sWlo[woff0];
            unsigned wlo1 = sWlo[woff1];
            mma_bf16(c[t], ahi, whi0, whi1);
            mma_bf16(c[t], ahi, wlo0, wlo1);
            mma_bf16(c[t], alo, whi0, whi1);
        }
    }

    // epilogue (fp16): c0,c1 -> row g, cols tig*2..+1 ; c2,c3 -> row g+8
#pragma unroll
    for (int t = 0; t < 8; t++) {
        int h0 = (bn + t * 8 + tig * 2) >> 1;   // half2 column index
        int row = bm + r0 + g;
        if (row < N_NODES)
            g_xwh[row * 64 + h0] = __floats2half2_rn(c[t][0], c[t][1]);
        if (row + 8 < N_NODES)
            g_xwh[(row + 8) * 64 + h0] = __floats2half2_rn(c[t][2], c[t][3]);
    }
}

// ---------------- aggregation + bias + leaky relu + BN stats --------------
// fp16 gathers (8B/lane) halve L2 traffic; fp32 accumulation.
__global__ __launch_bounds__(256) void agg_k(const float* __restrict__ bias, int sb) {
    __shared__ float s_sum[HID];
    __shared__ float s_sq[HID];
    int tid = threadIdx.x;
    GDC_LAUNCH();   // let the dependent (next gemm) run its W prologue early
    if (tid < HID) { s_sum[tid] = 0.f; s_sq[tid] = 0.f; }
    GDC_WAIT();     // predecessor (gemm / scatter) outputs complete
    __syncthreads();

    int node = blockIdx.x * 8 + (tid >> 5);  // 6250 blocks * 8 warps == 50000
    int lane = tid & 31;
    float dn = g_dnorm[node];
    int cbase = lane * 2;   // half2 column base (4 channels)

    uint2 sraw = *(const uint2*)&g_xwh[node * 64 + cbase];
    float2 sf0 = __half22float2(*(__half2*)&sraw.x);
    float2 sf1 = __half22float2(*(__half2*)&sraw.y);

    float4 a0 = make_float4(0.f, 0.f, 0.f, 0.f);
    float4 a1 = make_float4(0.f, 0.f, 0.f, 0.f);
    float4 a2 = make_float4(0.f, 0.f, 0.f, 0.f);
    float4 a3 = make_float4(0.f, 0.f, 0.f, 0.f);
    int s = g_rowptr[node], e = g_rowptr[node + 1];
    int i = s;
    for (; i + 3 < e; i += 4) {
        int2 c0 = g_csre[i];
        int2 c1 = g_csre[i + 1];
        int2 c2 = g_csre[i + 2];
        int2 c3 = g_csre[i + 3];
        uint2 r0 = *(const uint2*)&g_xwh[c0.x * 64 + cbase];
        uint2 r1 = *(const uint2*)&g_xwh[c1.x * 64 + cbase];
        uint2 r2 = *(const uint2*)&g_xwh[c2.x * 64 + cbase];
        uint2 r3 = *(const uint2*)&g_xwh[c3.x * 64 + cbase];
        float w0 = __int_as_float(c0.y);
        float w1 = __int_as_float(c1.y);
        float w2 = __int_as_float(c2.y);
        float w3 = __int_as_float(c3.y);
        float2 u00 = __half22float2(*(__half2*)&r0.x);
        float2 u01 = __half22float2(*(__half2*)&r0.y);
        float2 u10 = __half22float2(*(__half2*)&r1.x);
        float2 u11 = __half22float2(*(__half2*)&r1.y);
        float2 u20 = __half22float2(*(__half2*)&r2.x);
        float2 u21 = __half22float2(*(__half2*)&r2.y);
        float2 u30 = __half22float2(*(__half2*)&r3.x);
        float2 u31 = __half22float2(*(__half2*)&r3.y);
        a0.x = fmaf(w0, u00.x, a0.x); a0.y = fmaf(w0, u00.y, a0.y);
        a0.z = fmaf(w0, u01.x, a0.z); a0.w = fmaf(w0, u01.y, a0.w);
        a1.x = fmaf(w1, u10.x, a1.x); a1.y = fmaf(w1, u10.y, a1.y);
        a1.z = fmaf(w1, u11.x, a1.z); a1.w = fmaf(w1, u11.y, a1.w);
        a2.x = fmaf(w2, u20.x, a2.x); a2.y = fmaf(w2, u20.y, a2.y);
        a2.z = fmaf(w2, u21.x, a2.z); a2.w = fmaf(w2, u21.y, a2.w);
        a3.x = fmaf(w3, u30.x, a3.x); a3.y = fmaf(w3, u30.y, a3.y);
        a3.z = fmaf(w3, u31.x, a3.z); a3.w = fmaf(w3, u31.y, a3.w);
    }
    for (; i < e; i++) {
        int2 cc = g_csre[i];
        float ww = __int_as_float(cc.y);
        uint2 r = *(const uint2*)&g_xwh[cc.x * 64 + cbase];
        float2 u0 = __half22float2(*(__half2*)&r.x);
        float2 u1 = __half22float2(*(__half2*)&r.y);
        a0.x = fmaf(ww, u0.x, a0.x); a0.y = fmaf(ww, u0.y, a0.y);
        a0.z = fmaf(ww, u1.x, a0.z); a0.w = fmaf(ww, u1.y, a0.w);
    }
    float4 acc;
    acc.x = (a0.x + a1.x) + (a2.x + a3.x);
    acc.y = (a0.y + a1.y) + (a2.y + a3.y);
    acc.z = (a0.z + a1.z) + (a2.z + a3.z);
    acc.w = (a0.w + a1.w) + (a2.w + a3.w);

    float4 bv = *(const float4*)&bias[lane * 4];
    float dn2 = dn * dn;
    float4 y;
    y.x = dn * acc.x + dn2 * sf0.x + bv.x;
    y.y = dn * acc.y + dn2 * sf0.y + bv.y;
    y.z = dn * acc.z + dn2 * sf1.x + bv.z;
    y.w = dn * acc.w + dn2 * sf1.y + bv.w;
    // leaky relu 0.01
    y.x = y.x > 0.f ? y.x : 0.01f * y.x;
    y.y = y.y > 0.f ? y.y : 0.01f * y.y;
    y.z = y.z > 0.f ? y.z : 0.01f * y.z;
    y.w = y.w > 0.f ? y.w : 0.01f * y.w;
    *(float4*)&g_hbuf[node * 128 + lane * 4] = y;

    int c = lane * 4;
    atomicAdd(&s_sum[c + 0], y.x);
    atomicAdd(&s_sum[c + 1], y.y);
    atomicAdd(&s_sum[c + 2], y.z);
    atomicAdd(&s_sum[c + 3], y.w);
    atomicAdd(&s_sq[c + 0], y.x * y.x);
    atomicAdd(&s_sq[c + 1], y.y * y.y);
    atomicAdd(&s_sq[c + 2], y.z * y.z);
    atomicAdd(&s_sq[c + 3], y.w * y.w);
    __syncthreads();
    if (tid < HID) {
        atomicAdd(&g_stats2[sb][tid], s_sum[tid]);
        atomicAdd(&g_stats2[sb][HID + tid], s_sq[tid]);
    }
}

// ---------------- mean pool (binary search on sorted batch) ---------------
__device__ __forceinline__ int lower_bound_dev(const int* a, int n, int v) {
    int lo = 0, hi = n;
    while (lo < hi) {
        int m = (lo + hi) >> 1;
        if (a[m] < v) lo = m + 1; else hi = m;
    }
    return lo;
}

__global__ void pool_k(const int* __restrict__ batch,
                       const float* __restrict__ gamma,
                       const float* __restrict__ beta, int sb) {
    GDC_LAUNCH();
    GDC_WAIT();
    int g = blockIdx.x;
    __shared__ int se[2];
    if (threadIdx.x == 0) {
        se[0] = lower_bound_dev(batch, N_NODES, g);
        se[1] = lower_bound_dev(batch, N_NODES, g + 1);
    }
    __syncthreads();
    int s = se[0], e = se[1];
    int c = threadIdx.x;  // 128 threads
    const float inv = 1.0f / (float)N_NODES;
    float mu = g_stats2[sb][c] * inv;
    float var = g_stats2[sb][HID + c] * inv - mu * mu;
    float sc = rsqrtf(var + 1e-5f) * gamma[c];
    float sh = beta[c] - mu * sc;
    float acc = 0.f;
    for (int i = s; i < e; i++) acc += g_hbuf[i * 128 + c];
    float n = (float)(e - s);
    float cnt = fmaxf(n, 1.0f);
    g_gemb[g * 128 + c] = (sc * acc + sh * n) / cnt;
}

// ---------------- head GEMM (M=256, N=512, K in {128,512,768}) ------------
__device__ __forceinline__ float gelu_exact(float x) {
    return 0.5f * x * (1.0f + erff(x * 0.70710678118654752f));
}

__global__ __launch_bounds__(256) void gemm_head_k(int which,
                                                   const float* __restrict__ Aext,
                                                   const float* __restrict__ B,
                                                   const float* __restrict__ bias) {
    const float* A;
    float* C;
    const float* res;
    int K;
    bool use_gelu, hasres;
    if (which == 0)      { A = g_gemb; C = g_p1g; res = nullptr; K = 128; use_gelu = false; hasres = false; }
    else if (which == 1) { A = g_p1g;  C = g_h2g; res = g_p1g;   K = 512; use_gelu = true;  hasres = true; }
    else if (which == 2) { A = Aext;   C = g_p1t; res = nullptr; K = 768; use_gelu = false; hasres = false; }
    else                 { A = g_p1t;  C = g_h2t; res = g_p1t;   K = 512; use_gelu = true;  hasres = true; }
    const int N = PROJ;

    __shared__ float As[32][36];
    __shared__ float Bs[32][64];
    int bm = blockIdx.x * 32, bn = blockIdx.y * 64;
    int tid = threadIdx.x;
    int tx = tid & 15;   // cols tx*4
    int ty = tid >> 4;   // rows ty*2
    float acc[2][4];
#pragma unroll
    for (int i = 0; i < 2; i++)
#pragma unroll
        for (int j = 0; j < 4; j++) acc[i][j] = 0.f;

    for (int k0 = 0; k0 < K; k0 += 32) {
        {
            int m = tid >> 3, k4 = (tid & 7) << 2;
            float4 v = *(const float4*)&A[(bm + m) * K + k0 + k4];
            if (use_gelu) {
                v.x = gelu_exact(v.x);
                v.y = gelu_exact(v.y);
                v.z = gelu_exact(v.z);
                v.w = gelu_exact(v.w);
            }
            *(float4*)&As[m][k4] = v;
        }
#pragma unroll
        for (int t = tid; t < 512; t += 256) {
            int k = t >> 4, n4 = (t & 15) << 2;
            *(float4*)&Bs[k][n4] = *(const float4*)&B[(k0 + k) * N + bn + n4];
        }
        __syncthreads();
#pragma unroll
        for (int k = 0; k < 32; k++) {
            float a0 = As[ty * 2 + 0][k];
            float a1 = As[ty * 2 + 1][k];
            float4 b = *(float4*)&Bs[k][tx * 4];
            acc[0][0] = fmaf(a0, b.x, acc[0][0]);
            acc[0][1] = fmaf(a0, b.y, acc[0][1]);
            acc[0][2] = fmaf(a0, b.z, acc[0][2]);
            acc[0][3] = fmaf(a0, b.w, acc[0][3]);
            acc[1][0] = fmaf(a1, b.x, acc[1][0]);
            acc[1][1] = fmaf(a1, b.y, acc[1][1]);
            acc[1][2] = fmaf(a1, b.z, acc[1][2]);
            acc[1][3] = fmaf(a1, b.w, acc[1][3]);
        }
        __syncthreads();
    }
#pragma unroll
    for (int i = 0; i < 2; i++) {
        int row = bm + ty * 2 + i, col = bn + tx * 4;
        float4 bv = *(const float4*)&bias[col];
        float4 o = make_float4(acc[i][0] + bv.x, acc[i][1] + bv.y,
                               acc[i][2] + bv.z, acc[i][3] + bv.w);
        if (hasres) {
            float4 r = *(const float4*)&res[row * N + col];
            o.x += r.x; o.y += r.y; o.z += r.z; o.w += r.w;
        }
        *(float4*)&C[row * N + col] = o;
    }
}

// ---------------- fused LayerNorm(512) + classifier + log_softmax ---------
__global__ void ln_cls_k(const float* __restrict__ g_gamma, const float* __restrict__ g_beta,
                         const float* __restrict__ t_gamma, const float* __restrict__ t_beta,
                         const float* __restrict__ g_W, const float* __restrict__ g_b,
                         const float* __restrict__ t_W, const float* __restrict__ t_b,
                         float* __restrict__ out) {
    int rowg = blockIdx.x;
    int which = rowg >> 8;      // 0 = graph, 1 = text
    int row = rowg & 255;
    const float* X = which ? g_h2t : g_h2g;
    const float* gamma = which ? t_gamma : g_gamma;
    const float* beta  = which ? t_beta  : g_beta;
    const float* Wc    = which ? t_W : g_W;
    const float* bc    = which ? t_b : g_b;
    float* proj = out + which * (N_GRAPHS * PROJ) + row * PROJ;
    float* logp = out + 2 * (N_GRAPHS * PROJ) + which * (N_GRAPHS * N_CLS) + row * N_CLS;

    int tid = threadIdx.x;  // 128 threads, 4 elems each
    float4 v = *(const float4*)&X[row * 512 + tid * 4];
    float s = v.x + v.y + v.z + v.w;
    float q = v.x * v.x + v.y * v.y + v.z * v.z + v.w * v.w;
#pragma unroll
    for (int o = 16; o > 0; o >>= 1) {
        s += __shfl_xor_sync(0xffffffffu, s, o);
        q += __shfl_xor_sync(0xffffffffu, q, o);
    }
    __shared__ float ss[4], qq[4];
    __shared__ float srow[512];
    __shared__ float part[4][32];
    int warp = tid >> 5, lane = tid & 31;
    if (lane == 0) { ss[warp] = s; qq[warp] = q; }
    __syncthreads();
    s = ss[0] + ss[1] + ss[2] + ss[3];
    q = qq[0] + qq[1] + qq[2] + qq[3];
    float mean = s * (1.0f / 512.0f);
    float var = q * (1.0f / 512.0f) - mean * mean;
    float istd = rsqrtf(var + 1e-5f);
    float4 g4 = *(const float4*)&gamma[tid * 4];
    float4 b4 = *(const float4*)&beta[tid * 4];
    float4 o;
    o.x = (v.x - mean) * istd * g4.x + b4.x;
    o.y = (v.y - mean) * istd * g4.y + b4.y;
    o.z = (v.z - mean) * istd * g4.z + b4.z;
    o.w = (v.w - mean) * istd * g4.w + b4.w;
    *(float4*)&proj[tid * 4] = o;
    *(float4*)&srow[tid * 4] = o;
    __syncthreads();

    // classifier: quarter = warp, class = lane
    int c = lane;
    float acc = 0.f;
    const float* wp = Wc + (warp * 128) * 32 + c;
    const float* rp = srow + warp * 128;
#pragma unroll 8
    for (int k = 0; k < 128; k++) acc = fmaf(rp[k], wp[k * 32], acc);
    part[warp][c] = acc;
    __syncthreads();
    if (tid < 32) {
        float l = part[0][tid] + part[1][tid] + part[2][tid] + part[3][tid] + bc[tid];
        float mx = l;
#pragma unroll
        for (int o2 = 16; o2 > 0; o2 >>= 1)
            mx = fmaxf(mx, __shfl_xor_sync(0xffffffffu, mx, o2));
        float lm = l - mx;
        float ex = __expf(lm);
        float sm = ex;
#pragma unroll
        for (int o2 = 16; o2 > 0; o2 >>= 1)
            sm += __shfl_xor_sync(0xffffffffu, sm, o2);
        logp[tid] = lm - logf(sm);
    }
}

// ---------------- launch ---------------------------------------------------
extern "C" void kernel_launch(void* const* d_in, const int* in_sizes, int n_in,
                              void* d_out, int out_size) {
    const float* x       = (const float*)d_in[0];
    const int*   ei      = (const int*)d_in[1];
    const int*   src     = ei;
    const int*   dst     = ei + N_EDGES;
    const int*   batch   = (const int*)d_in[2];
    const float* text    = (const float*)d_in[3];
    const float* gcn_W   = (const float*)d_in[4];
    const float* gcn_b   = (const float*)d_in[5];
    const float* bn_g    = (const float*)d_in[6];
    const float* bn_b    = (const float*)d_in[7];
    const float* gpj_W1  = (const float*)d_in[8];
    const float* gpj_b1  = (const float*)d_in[9];
    const float* gpj_W2  = (const float*)d_in[10];
    const float* gpj_b2  = (const float*)d_in[11];
    const float* gpj_g   = (const float*)d_in[12];
    const float* gpj_be  = (const float*)d_in[13];
    const float* gcl_W   = (const float*)d_in[14];
    const float* gcl_b   = (const float*)d_in[15];
    const float* tpj_W1  = (const float*)d_in[16];
    const float* tpj_b1  = (const float*)d_in[17];
    const float* tpj_W2  = (const float*)d_in[18];
    const float* tpj_b2  = (const float*)d_in[19];
    const float* tpj_g   = (const float*)d_in[20];
    const float* tpj_be  = (const float*)d_in[21];
    const float* tcl_W   = (const float*)d_in[22];
    const float* tcl_b   = (const float*)d_in[23];
    float* out = (float*)d_out;

    // one-time host-side setup (no device memory)
    static cudaStream_t side = nullptr;
    static cudaEvent_t ev_fork, ev_gemm0, ev_text;
    if (!side) {
        cudaStreamCreateWithFlags(&side, cudaStreamNonBlocking);
        cudaEventCreateWithFlags(&ev_fork, cudaEventDisableTiming);
        cudaEventCreateWithFlags(&ev_gemm0, cudaEventDisableTiming);
        cudaEventCreateWithFlags(&ev_text, cudaEventDisableTiming);
        cudaFuncSetAttribute(gemm_node_mma_k,
                             cudaFuncAttributeMaxDynamicSharedMemorySize, GEMM_SMEM);
    }

    // PDL launch config (default stream)
    cudaLaunchAttribute pdl_attr;
    pdl_attr.id = cudaLaunchAttributeProgrammaticStreamSerialization;
    pdl_attr.val.programmaticStreamSerializationAllowed = 1;

    // ---- fork: side stream runs gemm L0 (needs only x) and the text head
    //      (needs only text) concurrently with the CSR build / GCN loop ----
    cudaEventRecord(ev_fork, 0);
    cudaStreamWaitEvent(side, ev_fork, 0);

    zero_cnt_k<<<196, 256>>>();                                   // main #1
    deg_count_k<<<(N_EDGES + 255) / 256, 256>>>(dst);             // main #2
    scan_part_k<<<196, 256>>>();                                  // main #3 (+dnorm)
    gemm_node_mma_k<<<(N_NODES + 63) / 64, 256, GEMM_SMEM, side>>>(
        x, 1, gcn_W, (const float*)nullptr, (const float*)nullptr, 0, 0);
    cudaEventRecord(ev_gemm0, side);
    // text head on side (independent of everything until ln_cls)
    dim3 hgrid(N_GRAPHS / 32, PROJ / 64);
    gemm_head_k<<<hgrid, 256, 0, side>>>(2, text, tpj_W1, tpj_b1);
    gemm_head_k<<<hgrid, 256, 0, side>>>(3, (const float*)nullptr, tpj_W2, tpj_b2);
    cudaEventRecord(ev_text, side);

    scan_add_k<<<196, 256>>>();                                   // main #4
    scatter_k<<<(N_EDGES + 255) / 256, 256>>>(src, dst);          // main #5

    // ---- GCN loop with PDL: agg l -> stats buf[l&1]; gemm l reads
    //      buf[(l-1)&1]; each gemm's W prologue overlaps the prior agg ----
    cudaStreamWaitEvent(0, ev_gemm0, 0);
    {
        cudaLaunchConfig_t cfg = {};
        cfg.blockDim = {256, 1, 1};
        cfg.stream = 0;
        cfg.attrs = &pdl_attr;
        cfg.numAttrs = 1;

        cfg.gridDim = {N_NODES / 8, 1, 1};
        cfg.dynamicSmemBytes = 0;
        cudaLaunchKernelEx(&cfg, agg_k, (const float*)gcn_b, 0);  // layer 0 agg
        for (int l = 1; l < 4; l++) {
            cfg.gridDim = {(N_NODES + 63) / 64, 1, 1};
            cfg.dynamicSmemBytes = GEMM_SMEM;
            cudaLaunchKernelEx(&cfg, gemm_node_mma_k,
                               (const float*)g_hbuf, 0,
                               (const float*)(gcn_W + l * 128 * 128),
                               (const float*)(bn_g + (l - 1) * 128),
                               (const float*)(bn_b + (l - 1) * 128),
                               (l - 1) & 1, l & 1);
            cfg.gridDim = {N_NODES / 8, 1, 1};
            cfg.dynamicSmemBytes = 0;
            cudaLaunchKernelEx(&cfg, agg_k, (const float*)(gcn_b + l * 128), l & 1);
        }

        // pool with PDL (predecessor agg3)
        cfg.gridDim = {N_GRAPHS, 1, 1};
        cfg.blockDim = {128, 1, 1};
        cfg.dynamicSmemBytes = 0;
        cudaLaunchKernelEx(&cfg, pool_k, batch,
                           (const float*)(bn_g + 3 * 128),
                           (const float*)(bn_b + 3 * 128), 1);
    }

    // ---- graph head ----
    gemm_head_k<<<hgrid, 256>>>(0, (const float*)nullptr, gpj_W1, gpj_b1);
    gemm_head_k<<<hgrid, 256>>>(1, (const float*)nullptr, gpj_W2, gpj_b2);

    // ---- join text branch, then fused LN + classifier + log_softmax ----
    cudaStreamWaitEvent(0, ev_text, 0);
    ln_cls_k<<<2 * N_GRAPHS, 128>>>(gpj_g, gpj_be, tpj_g, tpj_be,
                                    gcl_W, gcl_b, tcl_W, tcl_b, out);
}